// round 1
// baseline (speedup 1.0000x reference)
#include <cuda_runtime.h>
#include <cstdint>

#define BATCH 2
#define CCH   256
#define NPIX  4096      // 64*64
#define BA    8         // BATCH*AREA
#define NA    1024      // NPIX/AREA
#define NH    8
#define HD    32
#define EPS   1e-5f

// Scratch (device globals; no allocation allowed)
__device__ float g_Q[BA * NH * NA * HD];   // [ba][h][i][d]  8MB
__device__ float g_K[BA * NH * NA * HD];   // [ba][h][j][d]  8MB
__device__ float g_V[BA * NH * NA * HD];   // [ba][h][j][d]  8MB
__device__ float g_AO[BATCH * NPIX * CCH]; // [b][n][c]      8MB

// ---------------------------------------------------------------------------
// Input projection GEMM: Y[b,o,n] = BN( sum_c W[o,c] * X[b,c,n] )
// Tile 64(o) x 64(n) x 16(k), 256 threads, 4x4 micro-tile.
// is_qk=1: OC=512, o<256 -> Q, else K.  is_qk=0: OC=256 -> V.
// Output scattered into [ba][h][seq][d] layout.
// ---------------------------------------------------------------------------
__global__ __launch_bounds__(256) void proj_in_kernel(
    const float* __restrict__ x,   // [B][256][4096]
    const float* __restrict__ w,   // [OC][256]
    const float* __restrict__ gg, const float* __restrict__ bb,
    const float* __restrict__ mm, const float* __restrict__ vv,
    int is_qk)
{
    __shared__ float Xs[16][68];
    __shared__ float Ws[16][68];

    const int b  = blockIdx.z;
    const int o0 = blockIdx.y * 64;
    const int n0 = blockIdx.x * 64;
    const int t  = threadIdx.x;
    const int tx = t & 15, ty = t >> 4;

    const float* xb = x + (size_t)b * CCH * NPIX;

    float acc[4][4] = {};

    for (int k0 = 0; k0 < 256; k0 += 16) {
        // Xs[kk][nn] = x[b][k0+kk][n0+nn]   (coalesced read, conflict-free store)
        {
            int kk = t >> 4, c4 = (t & 15) * 4;
            float4 xv = *(const float4*)(xb + (size_t)(k0 + kk) * NPIX + n0 + c4);
            *(float4*)&Xs[kk][c4] = xv;
        }
        // Ws[kk][oo] = w[o0+oo][k0+kk]      (coalesced read, transpose store)
        {
            int oo = t >> 2, kq = (t & 3) * 4;
            float4 wv = *(const float4*)(w + (size_t)(o0 + oo) * 256 + k0 + kq);
            Ws[kq + 0][oo] = wv.x;
            Ws[kq + 1][oo] = wv.y;
            Ws[kq + 2][oo] = wv.z;
            Ws[kq + 3][oo] = wv.w;
        }
        __syncthreads();
        #pragma unroll
        for (int kk = 0; kk < 16; kk++) {
            float4 av = *(const float4*)&Ws[kk][ty * 4];
            float4 bv = *(const float4*)&Xs[kk][tx * 4];
            float a[4] = {av.x, av.y, av.z, av.w};
            float c[4] = {bv.x, bv.y, bv.z, bv.w};
            #pragma unroll
            for (int i = 0; i < 4; i++)
                #pragma unroll
                for (int j = 0; j < 4; j++)
                    acc[i][j] += a[i] * c[j];
        }
        __syncthreads();
    }

    // Epilogue: BN affine + scatter into attention layout
    #pragma unroll
    for (int i = 0; i < 4; i++) {
        int o = o0 + ty * 4 + i;
        float s  = gg[o] * rsqrtf(vv[o] + EPS);
        float sh = bb[o] - mm[o] * s;

        float* dst;
        int oc;
        if (is_qk) {
            if (o < 256) { dst = g_Q; oc = o; }
            else         { dst = g_K; oc = o - 256; }
        } else {
            dst = g_V; oc = o;
        }
        int h = oc >> 5, d = oc & 31;

        #pragma unroll
        for (int j = 0; j < 4; j++) {
            int n  = n0 + tx * 4 + j;
            int ba = b * 4 + (n >> 10);
            int na = n & 1023;
            dst[(((size_t)(ba * NH + h) * NA) + na) * HD + d] = acc[i][j] * s + sh;
        }
    }
}

// ---------------------------------------------------------------------------
// Attention: per (ba,h) pair, 1024x1024 scores, hd=32.
// 1 thread = 1 query row; online softmax; K/V staged 128 rows at a time.
// ---------------------------------------------------------------------------
__global__ __launch_bounds__(128, 4) void attn_kernel()
{
    __shared__ float Ks[128 * 32];
    __shared__ float Vs[128 * 32];

    const int bh = blockIdx.y;                    // 0..63 = ba*8+h
    const int t  = threadIdx.x;                   // 0..127
    const int i  = blockIdx.x * 128 + t;          // query row in [0,1024)
    const float scale = 0.17677669529663687f;     // 32^-0.5

    // Load (scaled) q row into registers
    float q[32];
    {
        const float* Qp = g_Q + ((size_t)bh * NA + i) * HD;
        #pragma unroll
        for (int d4 = 0; d4 < 8; d4++) {
            float4 v4 = *(const float4*)(Qp + d4 * 4);
            q[d4 * 4 + 0] = v4.x * scale;
            q[d4 * 4 + 1] = v4.y * scale;
            q[d4 * 4 + 2] = v4.z * scale;
            q[d4 * 4 + 3] = v4.w * scale;
        }
    }

    float acc[32];
    #pragma unroll
    for (int d = 0; d < 32; d++) acc[d] = 0.f;
    float mx = -1e30f, l = 0.f;

    for (int j0 = 0; j0 < NA; j0 += 128) {
        // Flat coalesced copy: smem layout == global layout ([j][d])
        const float4* Kp = (const float4*)(g_K + ((size_t)bh * NA + j0) * HD);
        const float4* Vp = (const float4*)(g_V + ((size_t)bh * NA + j0) * HD);
        #pragma unroll
        for (int u = 0; u < 8; u++) {
            ((float4*)Ks)[t + u * 128] = Kp[t + u * 128];
            ((float4*)Vs)[t + u * 128] = Vp[t + u * 128];
        }
        __syncthreads();

        #pragma unroll 1
        for (int js = 0; js < 128; js += 16) {
            float s[16];
            #pragma unroll
            for (int j = 0; j < 16; j++) {
                const float* kr = Ks + (js + j) * 32;
                float a0 = 0.f, a1 = 0.f;
                #pragma unroll
                for (int d4 = 0; d4 < 8; d4 += 2) {
                    float4 ka = *(const float4*)(kr + d4 * 4);
                    float4 kb = *(const float4*)(kr + d4 * 4 + 4);
                    a0 += q[d4 * 4 + 0] * ka.x;
                    a0 += q[d4 * 4 + 1] * ka.y;
                    a0 += q[d4 * 4 + 2] * ka.z;
                    a0 += q[d4 * 4 + 3] * ka.w;
                    a1 += q[d4 * 4 + 4] * kb.x;
                    a1 += q[d4 * 4 + 5] * kb.y;
                    a1 += q[d4 * 4 + 6] * kb.z;
                    a1 += q[d4 * 4 + 7] * kb.w;
                }
                s[j] = a0 + a1;
            }

            float tmax = s[0];
            #pragma unroll
            for (int j = 1; j < 16; j++) tmax = fmaxf(tmax, s[j]);
            float mNew = fmaxf(mx, tmax);
            float corr = __expf(mx - mNew);
            mx = mNew;
            l *= corr;
            #pragma unroll
            for (int d = 0; d < 32; d++) acc[d] *= corr;

            #pragma unroll
            for (int j = 0; j < 16; j++) {
                float p = __expf(s[j] - mNew);
                l += p;
                const float* vr = Vs + (js + j) * 32;
                #pragma unroll
                for (int d4 = 0; d4 < 8; d4++) {
                    float4 vv4 = *(const float4*)(vr + d4 * 4);
                    acc[d4 * 4 + 0] += p * vv4.x;
                    acc[d4 * 4 + 1] += p * vv4.y;
                    acc[d4 * 4 + 2] += p * vv4.z;
                    acc[d4 * 4 + 3] += p * vv4.w;
                }
            }
        }
        __syncthreads();
    }

    // Write AO[b][n][c]
    const float inv = 1.f / l;
    const int b    = bh >> 5;
    const int area = (bh >> 3) & 3;
    const int n    = area * NA + i;
    const int c    = (bh & 7) * HD;
    float* outp = g_AO + ((size_t)b * NPIX + n) * CCH + c;
    #pragma unroll
    for (int d4 = 0; d4 < 8; d4++) {
        float4 r;
        r.x = acc[d4 * 4 + 0] * inv;
        r.y = acc[d4 * 4 + 1] * inv;
        r.z = acc[d4 * 4 + 2] * inv;
        r.w = acc[d4 * 4 + 3] * inv;
        *(float4*)(outp + d4 * 4) = r;
    }
}

// ---------------------------------------------------------------------------
// Output projection: out[b,co,n] = BN( sum_c AO[b,n,c] * Wp[co,c] )
// ---------------------------------------------------------------------------
__global__ __launch_bounds__(256) void proj_out_kernel(
    const float* __restrict__ w,   // [256][256]
    const float* __restrict__ gg, const float* __restrict__ bb,
    const float* __restrict__ mm, const float* __restrict__ vv,
    float* __restrict__ out)       // [B][256][4096]
{
    __shared__ float As[16][68];   // [kk][nn]
    __shared__ float Ws[16][68];   // [kk][oo]

    const int b  = blockIdx.z;
    const int o0 = blockIdx.y * 64;     // co tile
    const int n0 = blockIdx.x * 64;     // pixel tile
    const int t  = threadIdx.x;
    const int tx = t & 15, ty = t >> 4;

    float acc[4][4] = {};

    for (int k0 = 0; k0 < 256; k0 += 16) {
        // As[kk][nn] = AO[b][n0+nn][k0+kk]   (transpose load)
        {
            int nn = t >> 2, kq = (t & 3) * 4;
            float4 av = *(const float4*)(g_AO + ((size_t)b * NPIX + n0 + nn) * CCH + k0 + kq);
            As[kq + 0][nn] = av.x;
            As[kq + 1][nn] = av.y;
            As[kq + 2][nn] = av.z;
            As[kq + 3][nn] = av.w;
        }
        // Ws[kk][oo] = w[o0+oo][k0+kk]
        {
            int oo = t >> 2, kq = (t & 3) * 4;
            float4 wv = *(const float4*)(w + (size_t)(o0 + oo) * 256 + k0 + kq);
            Ws[kq + 0][oo] = wv.x;
            Ws[kq + 1][oo] = wv.y;
            Ws[kq + 2][oo] = wv.z;
            Ws[kq + 3][oo] = wv.w;
        }
        __syncthreads();
        #pragma unroll
        for (int kk = 0; kk < 16; kk++) {
            float4 av = *(const float4*)&Ws[kk][ty * 4];   // co
            float4 bv = *(const float4*)&As[kk][tx * 4];   // n
            float a[4] = {av.x, av.y, av.z, av.w};
            float c[4] = {bv.x, bv.y, bv.z, bv.w};
            #pragma unroll
            for (int i = 0; i < 4; i++)
                #pragma unroll
                for (int j = 0; j < 4; j++)
                    acc[i][j] += a[i] * c[j];
        }
        __syncthreads();
    }

    #pragma unroll
    for (int i = 0; i < 4; i++) {
        int co = o0 + ty * 4 + i;
        float s  = gg[co] * rsqrtf(vv[co] + EPS);
        float sh = bb[co] - mm[co] * s;
        float4 r;
        r.x = acc[i][0] * s + sh;
        r.y = acc[i][1] * s + sh;
        r.z = acc[i][2] * s + sh;
        r.w = acc[i][3] * s + sh;
        *(float4*)(out + ((size_t)(b * CCH + co)) * NPIX + n0 + tx * 4) = r;
    }
}

// ---------------------------------------------------------------------------
extern "C" void kernel_launch(void* const* d_in, const int* in_sizes, int n_in,
                              void* d_out, int out_size)
{
    const float* x    = (const float*)d_in[0];
    const float* w_qk = (const float*)d_in[1];
    const float* g_qk = (const float*)d_in[2];
    const float* b_qk = (const float*)d_in[3];
    const float* m_qk = (const float*)d_in[4];
    const float* v_qk = (const float*)d_in[5];
    const float* w_v  = (const float*)d_in[6];
    const float* g_v  = (const float*)d_in[7];
    const float* b_v  = (const float*)d_in[8];
    const float* m_v  = (const float*)d_in[9];
    const float* v_v  = (const float*)d_in[10];
    const float* w_p  = (const float*)d_in[11];
    const float* g_p  = (const float*)d_in[12];
    const float* b_p  = (const float*)d_in[13];
    const float* m_p  = (const float*)d_in[14];
    const float* v_p  = (const float*)d_in[15];
    float* out = (float*)d_out;

    // QK projection: OC=512 -> 8 o-tiles
    proj_in_kernel<<<dim3(64, 8, BATCH), 256>>>(x, w_qk, g_qk, b_qk, m_qk, v_qk, 1);
    // V projection: OC=256 -> 4 o-tiles
    proj_in_kernel<<<dim3(64, 4, BATCH), 256>>>(x, w_v, g_v, b_v, m_v, v_v, 0);
    // Attention: 8 row-chunks x 64 (ba,h)
    attn_kernel<<<dim3(8, 64), 128>>>();
    // Output projection
    proj_out_kernel<<<dim3(64, 4, BATCH), 256>>>(w_p, g_p, b_p, m_p, v_p, out);
}

// round 5
// speedup vs baseline: 2.4762x; 2.4762x over previous
#include <cuda_runtime.h>
#include <cuda_fp16.h>
#include <cstdint>

#define BATCH 2
#define CCH   256
#define NPIX  4096      // 64*64
#define BA    8         // BATCH*AREA
#define NA    1024      // NPIX/AREA
#define NH    8
#define HD    32
#define EPS   1e-5f

// scale * log2(e) folded into Q at projection time so P = exp2(S - SHIFT)
#define QSCALE (0.17677669529663687f * 1.4426950408889634f)
#define ESHIFT 8.0f

// Scratch (device globals; no allocation allowed)
__device__ __half g_Qh[BA * NH * NA * HD];   // [bh][i][d]  pre-scaled, fp16
__device__ __half g_Kh[BA * NH * NA * HD];   // [bh][j][d]  fp16
__device__ __half g_Vh[BA * NH * HD * NA];   // [bh][d][j]  TRANSPOSED fp16
__device__ float  g_AO[BATCH * NPIX * CCH];  // [b][n][c]

// ---------------------------------------------------------------------------
// mma.sync m16n8k16 f16*f16 -> f32 (sm_80+ baseline; runs on tensor pipe)
// ---------------------------------------------------------------------------
__device__ __forceinline__ void mma16816(float& c0, float& c1, float& c2, float& c3,
                                         uint32_t a0, uint32_t a1, uint32_t a2, uint32_t a3,
                                         uint32_t b0, uint32_t b1)
{
    asm volatile(
        "mma.sync.aligned.m16n8k16.row.col.f32.f16.f16.f32 "
        "{%0,%1,%2,%3}, {%4,%5,%6,%7}, {%8,%9}, {%0,%1,%2,%3};"
        : "+f"(c0), "+f"(c1), "+f"(c2), "+f"(c3)
        : "r"(a0), "r"(a1), "r"(a2), "r"(a3), "r"(b0), "r"(b1));
}

__device__ __forceinline__ float ex2f(float x) {
    float r;
    asm("ex2.approx.ftz.f32 %0, %1;" : "=f"(r) : "f"(x));
    return r;
}

// pack two fp32 into one f16x2 register (PTX operand order: hi, lo)
__device__ __forceinline__ uint32_t pack_h2(float lo, float hi) {
    uint32_t r;
    asm("cvt.rn.f16x2.f32 %0, %1, %2;" : "=r"(r) : "f"(hi), "f"(lo));
    return r;
}

// ---------------------------------------------------------------------------
// Input projection GEMM (fp32 SIMT): Y[b,o,n] = BN( sum_c W[o,c] * X[b,c,n] )
// is_qk=1: OC=512, o<256 -> Qh (pre-scaled), else Kh.  is_qk=0 -> Vh (transposed).
// ---------------------------------------------------------------------------
__global__ __launch_bounds__(256) void proj_in_kernel(
    const float* __restrict__ x,   // [B][256][4096]
    const float* __restrict__ w,   // [OC][256]
    const float* __restrict__ gg, const float* __restrict__ bb,
    const float* __restrict__ mm, const float* __restrict__ vv,
    int is_qk)
{
    __shared__ float Xs[16][68];
    __shared__ float Ws[16][68];

    const int b  = blockIdx.z;
    const int o0 = blockIdx.y * 64;
    const int n0 = blockIdx.x * 64;
    const int t  = threadIdx.x;
    const int tx = t & 15, ty = t >> 4;

    const float* xb = x + (size_t)b * CCH * NPIX;

    float acc[4][4] = {};

    for (int k0 = 0; k0 < 256; k0 += 16) {
        {
            int kk = t >> 4, c4 = (t & 15) * 4;
            float4 xv = *(const float4*)(xb + (size_t)(k0 + kk) * NPIX + n0 + c4);
            *(float4*)&Xs[kk][c4] = xv;
        }
        {
            int oo = t >> 2, kq = (t & 3) * 4;
            float4 wv = *(const float4*)(w + (size_t)(o0 + oo) * 256 + k0 + kq);
            Ws[kq + 0][oo] = wv.x;
            Ws[kq + 1][oo] = wv.y;
            Ws[kq + 2][oo] = wv.z;
            Ws[kq + 3][oo] = wv.w;
        }
        __syncthreads();
        #pragma unroll
        for (int kk = 0; kk < 16; kk++) {
            float4 av = *(const float4*)&Ws[kk][ty * 4];
            float4 bv = *(const float4*)&Xs[kk][tx * 4];
            float a[4] = {av.x, av.y, av.z, av.w};
            float c[4] = {bv.x, bv.y, bv.z, bv.w};
            #pragma unroll
            for (int i = 0; i < 4; i++)
                #pragma unroll
                for (int j = 0; j < 4; j++)
                    acc[i][j] += a[i] * c[j];
        }
        __syncthreads();
    }

    #pragma unroll
    for (int i = 0; i < 4; i++) {
        int o = o0 + ty * 4 + i;
        float s  = gg[o] * rsqrtf(vv[o] + EPS);
        float sh = bb[o] - mm[o] * s;

        #pragma unroll
        for (int j = 0; j < 4; j++) {
            int n  = n0 + tx * 4 + j;
            int ba = b * 4 + (n >> 10);
            int na = n & 1023;
            float val = acc[i][j] * s + sh;
            if (is_qk) {
                if (o < 256) {
                    int h = o >> 5, d = o & 31;
                    g_Qh[(((size_t)(ba * NH + h) * NA) + na) * HD + d] = __float2half_rn(val * QSCALE);
                } else {
                    int oc = o - 256, h = oc >> 5, d = oc & 31;
                    g_Kh[(((size_t)(ba * NH + h) * NA) + na) * HD + d] = __float2half_rn(val);
                }
            } else {
                int h = o >> 5, d = o & 31;
                g_Vh[(((size_t)(ba * NH + h) * HD) + d) * NA + na] = __float2half_rn(val);
            }
        }
    }
}

// ---------------------------------------------------------------------------
// Attention via mma.sync fp16.
// Grid (8 q-tiles, 64 bh), 256 threads = 8 warps, each warp owns 16 q rows.
// KV staged 128 rows/chunk: K [j][d] pitch 80B, V^T [d][j] pitch 272B
// (both pitches chosen for conflict-free half2 fragment loads).
// No-max softmax: P = exp2(S - 8), shift cancels in normalization.
// ---------------------------------------------------------------------------
__global__ __launch_bounds__(256) void attn_mma()
{
    __shared__ __align__(16) unsigned char Ks[128 * 80];   // 10240 B
    __shared__ __align__(16) unsigned char Vs[32 * 272];   //  8704 B

    const int t    = threadIdx.x;
    const int wid  = t >> 5;
    const int lane = t & 31;
    const int gr   = lane >> 2;      // group row 0..7
    const int tg   = lane & 3;       // thread-in-group
    const int bh   = blockIdx.y;
    const int q0   = blockIdx.x * 128;
    const int i0   = q0 + wid * 16;

    const __half* Qg = g_Qh + ((size_t)bh * NA + i0) * HD;
    const __half* Kg = g_Kh + (size_t)bh * NA * HD;
    const __half* Vg = g_Vh + (size_t)bh * HD * NA;

    // ---- Q A-fragments (2 k-tiles of 16), direct from global ----
    uint32_t qa[2][4];
    #pragma unroll
    for (int kt = 0; kt < 2; kt++) {
        qa[kt][0] = *(const uint32_t*)(Qg + (gr    ) * HD + kt * 16 + 2 * tg    );
        qa[kt][1] = *(const uint32_t*)(Qg + (gr + 8) * HD + kt * 16 + 2 * tg    );
        qa[kt][2] = *(const uint32_t*)(Qg + (gr    ) * HD + kt * 16 + 2 * tg + 8);
        qa[kt][3] = *(const uint32_t*)(Qg + (gr + 8) * HD + kt * 16 + 2 * tg + 8);
    }

    float o[4][4];
    #pragma unroll
    for (int dt = 0; dt < 4; dt++)
        #pragma unroll
        for (int c = 0; c < 4; c++) o[dt][c] = 0.f;
    float ls0 = 0.f, ls1 = 0.f;

    #pragma unroll 1
    for (int it = 0; it < 8; it++) {
        const int j0 = it * 128;
        __syncthreads();
        // stage K chunk: 128 rows x 64B -> pitch 80B
        #pragma unroll
        for (int u = 0; u < 2; u++) {
            int idx = t + u * 256;          // 0..511
            int row = idx >> 2, part = idx & 3;
            *(uint4*)(Ks + row * 80 + part * 16) =
                *(const uint4*)(Kg + (size_t)(j0 + row) * HD + part * 8);
        }
        // stage V^T chunk: 32 rows x 256B -> pitch 272B
        #pragma unroll
        for (int u = 0; u < 2; u++) {
            int idx = t + u * 256;
            int row = idx >> 4, part = idx & 15;
            *(uint4*)(Vs + row * 272 + part * 16) =
                *(const uint4*)(Vg + (size_t)row * NA + j0 + part * 8);
        }
        __syncthreads();

        #pragma unroll
        for (int m = 0; m < 8; m++) {       // 16-kv-column pairs
            float s[2][4];
            #pragma unroll
            for (int hlf = 0; hlf < 2; hlf++) {
                const int nt = 2 * m + hlf;
                float c0 = 0.f, c1 = 0.f, c2 = 0.f, c3 = 0.f;
                #pragma unroll
                for (int kt = 0; kt < 2; kt++) {
                    const unsigned char* kb = Ks + (nt * 8 + gr) * 80 + kt * 32 + 4 * tg;
                    uint32_t b0 = *(const uint32_t*)(kb);
                    uint32_t b1 = *(const uint32_t*)(kb + 16);
                    mma16816(c0, c1, c2, c3,
                             qa[kt][0], qa[kt][1], qa[kt][2], qa[kt][3], b0, b1);
                }
                s[hlf][0] = c0; s[hlf][1] = c1; s[hlf][2] = c2; s[hlf][3] = c3;
            }

            // softmax numerator: p = exp2(s - 8); accumulate row sums
            #pragma unroll
            for (int hlf = 0; hlf < 2; hlf++) {
                #pragma unroll
                for (int c = 0; c < 4; c++) s[hlf][c] = ex2f(s[hlf][c] - ESHIFT);
                ls0 += s[hlf][0] + s[hlf][1];
                ls1 += s[hlf][2] + s[hlf][3];
            }

            // P fragments: C-layout of tile pair == A-layout of 16x16 operand
            uint32_t pa0 = pack_h2(s[0][0], s[0][1]);
            uint32_t pa1 = pack_h2(s[0][2], s[0][3]);
            uint32_t pa2 = pack_h2(s[1][0], s[1][1]);
            uint32_t pa3 = pack_h2(s[1][2], s[1][3]);

            // O += P . V   (V^T rows = d, cols = j)
            #pragma unroll
            for (int dt = 0; dt < 4; dt++) {
                const unsigned char* vb = Vs + (dt * 8 + gr) * 272 + m * 32 + 4 * tg;
                uint32_t b0 = *(const uint32_t*)(vb);
                uint32_t b1 = *(const uint32_t*)(vb + 16);
                mma16816(o[dt][0], o[dt][1], o[dt][2], o[dt][3],
                         pa0, pa1, pa2, pa3, b0, b1);
            }
        }
    }

    // ---- normalize + write AO[b][n][c] ----
    ls0 += __shfl_xor_sync(0xFFFFFFFFu, ls0, 1);
    ls0 += __shfl_xor_sync(0xFFFFFFFFu, ls0, 2);
    ls1 += __shfl_xor_sync(0xFFFFFFFFu, ls1, 1);
    ls1 += __shfl_xor_sync(0xFFFFFFFFu, ls1, 2);
    const float inv0 = 1.f / ls0;
    const float inv1 = 1.f / ls1;

    const int b = bh >> 5, area = (bh >> 3) & 3, h = bh & 7;
    const int nb = area * NA + i0;
    float* outp = g_AO + ((size_t)b * NPIX + nb) * CCH + h * HD;
    #pragma unroll
    for (int dt = 0; dt < 4; dt++) {
        float2 r0, r1;
        r0.x = o[dt][0] * inv0; r0.y = o[dt][1] * inv0;
        r1.x = o[dt][2] * inv1; r1.y = o[dt][3] * inv1;
        *(float2*)(outp + (size_t)(gr    ) * CCH + dt * 8 + 2 * tg) = r0;
        *(float2*)(outp + (size_t)(gr + 8) * CCH + dt * 8 + 2 * tg) = r1;
    }
}

// ---------------------------------------------------------------------------
// Output projection (fp32 SIMT): out[b,co,n] = BN( sum_c AO[b,n,c] * Wp[co,c] )
// ---------------------------------------------------------------------------
__global__ __launch_bounds__(256) void proj_out_kernel(
    const float* __restrict__ w,
    const float* __restrict__ gg, const float* __restrict__ bb,
    const float* __restrict__ mm, const float* __restrict__ vv,
    float* __restrict__ out)
{
    __shared__ float As[16][68];
    __shared__ float Ws[16][68];

    const int b  = blockIdx.z;
    const int o0 = blockIdx.y * 64;
    const int n0 = blockIdx.x * 64;
    const int t  = threadIdx.x;
    const int tx = t & 15, ty = t >> 4;

    float acc[4][4] = {};

    for (int k0 = 0; k0 < 256; k0 += 16) {
        {
            int nn = t >> 2, kq = (t & 3) * 4;
            float4 av = *(const float4*)(g_AO + ((size_t)b * NPIX + n0 + nn) * CCH + k0 + kq);
            As[kq + 0][nn] = av.x;
            As[kq + 1][nn] = av.y;
            As[kq + 2][nn] = av.z;
            As[kq + 3][nn] = av.w;
        }
        {
            int oo = t >> 2, kq = (t & 3) * 4;
            float4 wv = *(const float4*)(w + (size_t)(o0 + oo) * 256 + k0 + kq);
            Ws[kq + 0][oo] = wv.x;
            Ws[kq + 1][oo] = wv.y;
            Ws[kq + 2][oo] = wv.z;
            Ws[kq + 3][oo] = wv.w;
        }
        __syncthreads();
        #pragma unroll
        for (int kk = 0; kk < 16; kk++) {
            float4 av = *(const float4*)&Ws[kk][ty * 4];
            float4 bv = *(const float4*)&As[kk][tx * 4];
            float a[4] = {av.x, av.y, av.z, av.w};
            float c[4] = {bv.x, bv.y, bv.z, bv.w};
            #pragma unroll
            for (int i = 0; i < 4; i++)
                #pragma unroll
                for (int j = 0; j < 4; j++)
                    acc[i][j] += a[i] * c[j];
        }
        __syncthreads();
    }

    #pragma unroll
    for (int i = 0; i < 4; i++) {
        int co = o0 + ty * 4 + i;
        float s  = gg[co] * rsqrtf(vv[co] + EPS);
        float sh = bb[co] - mm[co] * s;
        float4 r;
        r.x = acc[i][0] * s + sh;
        r.y = acc[i][1] * s + sh;
        r.z = acc[i][2] * s + sh;
        r.w = acc[i][3] * s + sh;
        *(float4*)(out + ((size_t)(b * CCH + co)) * NPIX + n0 + tx * 4) = r;
    }
}

// ---------------------------------------------------------------------------
extern "C" void kernel_launch(void* const* d_in, const int* in_sizes, int n_in,
                              void* d_out, int out_size)
{
    const float* x    = (const float*)d_in[0];
    const float* w_qk = (const float*)d_in[1];
    const float* g_qk = (const float*)d_in[2];
    const float* b_qk = (const float*)d_in[3];
    const float* m_qk = (const float*)d_in[4];
    const float* v_qk = (const float*)d_in[5];
    const float* w_v  = (const float*)d_in[6];
    const float* g_v  = (const float*)d_in[7];
    const float* b_v  = (const float*)d_in[8];
    const float* m_v  = (const float*)d_in[9];
    const float* v_v  = (const float*)d_in[10];
    const float* w_p  = (const float*)d_in[11];
    const float* g_p  = (const float*)d_in[12];
    const float* b_p  = (const float*)d_in[13];
    const float* m_p  = (const float*)d_in[14];
    const float* v_p  = (const float*)d_in[15];
    float* out = (float*)d_out;

    proj_in_kernel<<<dim3(64, 8, BATCH), 256>>>(x, w_qk, g_qk, b_qk, m_qk, v_qk, 1);
    proj_in_kernel<<<dim3(64, 4, BATCH), 256>>>(x, w_v, g_v, b_v, m_v, v_v, 0);
    attn_mma<<<dim3(8, 64), 256>>>();
    proj_out_kernel<<<dim3(64, 4, BATCH), 256>>>(w_p, g_p, b_p, m_p, v_p, out);
}

// round 6
// speedup vs baseline: 6.2368x; 2.5187x over previous
#include <cuda_runtime.h>
#include <cuda_fp16.h>
#include <cstdint>

#define BATCH 2
#define CCH   256
#define NPIX  4096      // 64*64
#define BA    8         // BATCH*AREA
#define NA    1024      // NPIX/AREA
#define NH    8
#define HD    32
#define EPS   1e-5f

// scale * log2(e) folded into W_q rows so P = exp2(S - SHIFT)
#define QSCALE (0.17677669529663687f * 1.4426950408889634f)
#define ESHIFT 8.0f

// Scratch (device globals; no allocation allowed)
__device__ __half g_Qh[BA * NH * NA * HD];    // [bh][i][d]  pre-scaled fp16
__device__ __half g_Kh[BA * NH * NA * HD];    // [bh][j][d]  fp16
__device__ __half g_Vh[BA * NH * HD * NA];    // [bh][d][j]  TRANSPOSED fp16
__device__ __half g_AOh[BATCH * NPIX * CCH];  // [b][n][c]   fp16
__device__ __half g_xh[BATCH * CCH * NPIX];   // [b][c][n]   fp16
__device__ __half g_Wh[768 * 256];            // rows 0-511 = BN-folded w_qk (Q rows xQSCALE), 512-767 = w_v
__device__ __half g_Whp[256 * 256];           // BN-folded w_p
__device__ float  g_sh[768];                  // shifts for qk/v
__device__ float  g_shp[256];                 // shifts for p

// ---------------------------------------------------------------------------
// PTX helpers
// ---------------------------------------------------------------------------
__device__ __forceinline__ void mma16816(float& c0, float& c1, float& c2, float& c3,
                                         uint32_t a0, uint32_t a1, uint32_t a2, uint32_t a3,
                                         uint32_t b0, uint32_t b1)
{
    asm volatile(
        "mma.sync.aligned.m16n8k16.row.col.f32.f16.f16.f32 "
        "{%0,%1,%2,%3}, {%4,%5,%6,%7}, {%8,%9}, {%0,%1,%2,%3};"
        : "+f"(c0), "+f"(c1), "+f"(c2), "+f"(c3)
        : "r"(a0), "r"(a1), "r"(a2), "r"(a3), "r"(b0), "r"(b1));
}

__device__ __forceinline__ float ex2f(float x) {
    float r;
    asm("ex2.approx.ftz.f32 %0, %1;" : "=f"(r) : "f"(x));
    return r;
}

__device__ __forceinline__ uint32_t pack_h2(float lo, float hi) {
    uint32_t r;
    asm("cvt.rn.f16x2.f32 %0, %1, %2;" : "=r"(r) : "f"(hi), "f"(lo));
    return r;
}

__device__ __forceinline__ uint32_t cvta_sh(const void* p) {
    return (uint32_t)__cvta_generic_to_shared(p);
}

#define LDMX4(r0,r1,r2,r3,addr) \
    asm volatile("ldmatrix.sync.aligned.m8n8.x4.shared.b16 {%0,%1,%2,%3}, [%4];" \
        : "=r"(r0),"=r"(r1),"=r"(r2),"=r"(r3) : "r"(addr))
#define LDMX4T(r0,r1,r2,r3,addr) \
    asm volatile("ldmatrix.sync.aligned.m8n8.x4.trans.shared.b16 {%0,%1,%2,%3}, [%4];" \
        : "=r"(r0),"=r"(r1),"=r"(r2),"=r"(r3) : "r"(addr))

// ---------------------------------------------------------------------------
// Prepass: fold BN into weights, convert to fp16; compute shift vectors.
// grid = 1024 blocks (rows), 256 threads (cols).
// ---------------------------------------------------------------------------
__global__ void prep_w(
    const float* __restrict__ w_qk, const float* __restrict__ g_qk, const float* __restrict__ b_qk,
    const float* __restrict__ m_qk, const float* __restrict__ v_qk,
    const float* __restrict__ w_v,  const float* __restrict__ g_v,  const float* __restrict__ b_v,
    const float* __restrict__ m_v,  const float* __restrict__ v_v,
    const float* __restrict__ w_p,  const float* __restrict__ g_p,  const float* __restrict__ b_p,
    const float* __restrict__ m_p,  const float* __restrict__ v_p)
{
    const int row = blockIdx.x;
    const int c   = threadIdx.x;
    const float *w, *g, *b, *m, *v;
    __half* dst; float* shd;
    int r; float extra = 1.f;
    if (row < 512) {
        w = w_qk; g = g_qk; b = b_qk; m = m_qk; v = v_qk;
        r = row; dst = g_Wh + (size_t)row * 256; shd = g_sh + row;
        if (row < 256) extra = QSCALE;
    } else if (row < 768) {
        w = w_v; g = g_v; b = b_v; m = m_v; v = v_v;
        r = row - 512; dst = g_Wh + (size_t)row * 256; shd = g_sh + row;
    } else {
        w = w_p; g = g_p; b = b_p; m = m_p; v = v_p;
        r = row - 768; dst = g_Whp + (size_t)r * 256; shd = g_shp + r;
    }
    float s0 = g[r] * rsqrtf(v[r] + EPS);
    dst[c] = __float2half_rn(w[(size_t)r * 256 + c] * s0 * extra);
    if (c == 0) *shd = (b[r] - m[r] * s0) * extra;
}

// x -> fp16, same layout. 2048 blocks x 256 threads x 4 elems.
__global__ void prep_x(const float* __restrict__ x)
{
    const int i = (blockIdx.x * 256 + threadIdx.x) * 4;
    float4 v = *(const float4*)(x + i);
    __half2* d = (__half2*)(g_xh + i);
    d[0] = __floats2half2_rn(v.x, v.y);
    d[1] = __floats2half2_rn(v.z, v.w);
}

// ---------------------------------------------------------------------------
// proj_in via mma.sync: Y[o,n] = Wh[o,:] . xh[b,:,n] + sh[o], o in [0,768)
// CTA 128o x 64n, k chunks of 64. 8 warps -> 32x32 each.
// ---------------------------------------------------------------------------
__global__ __launch_bounds__(256) void proj_in_mma()
{
    __shared__ __align__(16) __half Ws[128][72];
    __shared__ __align__(16) __half Xs[64][72];

    const int b  = blockIdx.z;
    const int o0 = blockIdx.y * 128;
    const int n0 = blockIdx.x * 64;
    const int t    = threadIdx.x;
    const int lane = t & 31, wid = t >> 5;
    const int wo = wid >> 1, wn = wid & 1;
    const int gr = lane >> 2, tg = lane & 3;

    const __half* xb = g_xh + (size_t)b * CCH * NPIX;

    float acc[2][4][4];
    #pragma unroll
    for (int i = 0; i < 2; i++)
        #pragma unroll
        for (int j = 0; j < 4; j++)
            #pragma unroll
            for (int k = 0; k < 4; k++) acc[i][j][k] = 0.f;

    for (int k0 = 0; k0 < 256; k0 += 64) {
        if (k0) __syncthreads();
        // stage W tile: 128 rows x 64 halves
        #pragma unroll
        for (int u = 0; u < 4; u++) {
            int idx = t + u * 256;
            int row = idx >> 3, seg = idx & 7;
            *(uint4*)&Ws[row][seg * 8] =
                *(const uint4*)(g_Wh + (size_t)(o0 + row) * 256 + k0 + seg * 8);
        }
        // stage X tile: 64 k-rows x 64 n halves
        #pragma unroll
        for (int u = 0; u < 2; u++) {
            int idx = t + u * 256;
            int row = idx >> 3, seg = idx & 7;
            *(uint4*)&Xs[row][seg * 8] =
                *(const uint4*)(xb + (size_t)(k0 + row) * NPIX + n0 + seg * 8);
        }
        __syncthreads();

        #pragma unroll
        for (int k16 = 0; k16 < 4; k16++) {
            uint32_t a[2][4];
            #pragma unroll
            for (int ot = 0; ot < 2; ot++) {
                uint32_t addr = cvta_sh(&Ws[wo * 32 + ot * 16 + (lane & 15)]
                                           [k16 * 16 + ((lane >> 4) << 3)]);
                LDMX4(a[ot][0], a[ot][1], a[ot][2], a[ot][3], addr);
            }
            uint32_t bf[2][4];
            #pragma unroll
            for (int nt = 0; nt < 2; nt++) {
                uint32_t addr = cvta_sh(&Xs[k16 * 16 + (lane & 15)]
                                           [wn * 32 + nt * 16 + ((lane >> 4) << 3)]);
                LDMX4T(bf[nt][0], bf[nt][1], bf[nt][2], bf[nt][3], addr);
            }
            #pragma unroll
            for (int ot = 0; ot < 2; ot++)
                #pragma unroll
                for (int nt = 0; nt < 2; nt++)
                    #pragma unroll
                    for (int nh = 0; nh < 2; nh++) {
                        int ni = nt * 2 + nh;
                        mma16816(acc[ot][ni][0], acc[ot][ni][1], acc[ot][ni][2], acc[ot][ni][3],
                                 a[ot][0], a[ot][1], a[ot][2], a[ot][3],
                                 bf[nt][nh * 2], bf[nt][nh * 2 + 1]);
                    }
        }
    }

    // epilogue: add shift, scatter to attention layouts
    #pragma unroll
    for (int ot = 0; ot < 2; ot++) {
        const int og = o0 + wo * 32 + ot * 16 + gr;   // rows og and og+8
        const float sh0 = g_sh[og], sh1 = g_sh[og + 8];
        if (o0 < 512) {
            __half* dst = (o0 < 256) ? g_Qh : g_Kh;
            const int ob0 = og & 255, ob1 = (og + 8) & 255;
            const int h0 = ob0 >> 5, d0 = ob0 & 31;
            const int h1 = ob1 >> 5, d1 = ob1 & 31;
            #pragma unroll
            for (int ni = 0; ni < 4; ni++) {
                int n  = n0 + wn * 32 + (ni >> 1) * 16 + (ni & 1) * 8 + 2 * tg;
                int ba = b * 4 + (n >> 10), na = n & 1023;
                size_t base = (size_t)(ba * NH) * NA * HD;
                dst[base + ((size_t)h0 * NA + na    ) * HD + d0] = __float2half_rn(acc[ot][ni][0] + sh0);
                dst[base + ((size_t)h0 * NA + na + 1) * HD + d0] = __float2half_rn(acc[ot][ni][1] + sh0);
                dst[base + ((size_t)h1 * NA + na    ) * HD + d1] = __float2half_rn(acc[ot][ni][2] + sh1);
                dst[base + ((size_t)h1 * NA + na + 1) * HD + d1] = __float2half_rn(acc[ot][ni][3] + sh1);
            }
        } else {
            const int oc0 = og - 512, oc1 = og - 512 + 8;
            const int h0 = oc0 >> 5, d0 = oc0 & 31;
            const int h1 = oc1 >> 5, d1 = oc1 & 31;
            #pragma unroll
            for (int ni = 0; ni < 4; ni++) {
                int n  = n0 + wn * 32 + (ni >> 1) * 16 + (ni & 1) * 8 + 2 * tg;
                int ba = b * 4 + (n >> 10), na = n & 1023;
                *(__half2*)&g_Vh[(((size_t)(ba * NH + h0)) * HD + d0) * NA + na] =
                    __floats2half2_rn(acc[ot][ni][0] + sh0, acc[ot][ni][1] + sh0);
                *(__half2*)&g_Vh[(((size_t)(ba * NH + h1)) * HD + d1) * NA + na] =
                    __floats2half2_rn(acc[ot][ni][2] + sh1, acc[ot][ni][3] + sh1);
            }
        }
    }
}

// ---------------------------------------------------------------------------
// Attention via mma.sync fp16 (unchanged core; epilogue now writes fp16 AO).
// ---------------------------------------------------------------------------
__global__ __launch_bounds__(256) void attn_mma()
{
    __shared__ __align__(16) unsigned char Ks[128 * 80];   // 10240 B
    __shared__ __align__(16) unsigned char Vs[32 * 272];   //  8704 B

    const int t    = threadIdx.x;
    const int wid  = t >> 5;
    const int lane = t & 31;
    const int gr   = lane >> 2;
    const int tg   = lane & 3;
    const int bh   = blockIdx.y;
    const int q0   = blockIdx.x * 128;
    const int i0   = q0 + wid * 16;

    const __half* Qg = g_Qh + ((size_t)bh * NA + i0) * HD;
    const __half* Kg = g_Kh + (size_t)bh * NA * HD;
    const __half* Vg = g_Vh + (size_t)bh * HD * NA;

    uint32_t qa[2][4];
    #pragma unroll
    for (int kt = 0; kt < 2; kt++) {
        qa[kt][0] = *(const uint32_t*)(Qg + (gr    ) * HD + kt * 16 + 2 * tg    );
        qa[kt][1] = *(const uint32_t*)(Qg + (gr + 8) * HD + kt * 16 + 2 * tg    );
        qa[kt][2] = *(const uint32_t*)(Qg + (gr    ) * HD + kt * 16 + 2 * tg + 8);
        qa[kt][3] = *(const uint32_t*)(Qg + (gr + 8) * HD + kt * 16 + 2 * tg + 8);
    }

    float o[4][4];
    #pragma unroll
    for (int dt = 0; dt < 4; dt++)
        #pragma unroll
        for (int c = 0; c < 4; c++) o[dt][c] = 0.f;
    float ls0 = 0.f, ls1 = 0.f;

    #pragma unroll 1
    for (int it = 0; it < 8; it++) {
        const int j0 = it * 128;
        __syncthreads();
        #pragma unroll
        for (int u = 0; u < 2; u++) {
            int idx = t + u * 256;
            int row = idx >> 2, part = idx & 3;
            *(uint4*)(Ks + row * 80 + part * 16) =
                *(const uint4*)(Kg + (size_t)(j0 + row) * HD + part * 8);
        }
        #pragma unroll
        for (int u = 0; u < 2; u++) {
            int idx = t + u * 256;
            int row = idx >> 4, part = idx & 15;
            *(uint4*)(Vs + row * 272 + part * 16) =
                *(const uint4*)(Vg + (size_t)row * NA + j0 + part * 8);
        }
        __syncthreads();

        #pragma unroll
        for (int m = 0; m < 8; m++) {
            float s[2][4];
            #pragma unroll
            for (int hlf = 0; hlf < 2; hlf++) {
                const int nt = 2 * m + hlf;
                float c0 = 0.f, c1 = 0.f, c2 = 0.f, c3 = 0.f;
                #pragma unroll
                for (int kt = 0; kt < 2; kt++) {
                    const unsigned char* kb = Ks + (nt * 8 + gr) * 80 + kt * 32 + 4 * tg;
                    uint32_t b0 = *(const uint32_t*)(kb);
                    uint32_t b1 = *(const uint32_t*)(kb + 16);
                    mma16816(c0, c1, c2, c3,
                             qa[kt][0], qa[kt][1], qa[kt][2], qa[kt][3], b0, b1);
                }
                s[hlf][0] = c0; s[hlf][1] = c1; s[hlf][2] = c2; s[hlf][3] = c3;
            }

            #pragma unroll
            for (int hlf = 0; hlf < 2; hlf++) {
                #pragma unroll
                for (int c = 0; c < 4; c++) s[hlf][c] = ex2f(s[hlf][c] - ESHIFT);
                ls0 += s[hlf][0] + s[hlf][1];
                ls1 += s[hlf][2] + s[hlf][3];
            }

            uint32_t pa0 = pack_h2(s[0][0], s[0][1]);
            uint32_t pa1 = pack_h2(s[0][2], s[0][3]);
            uint32_t pa2 = pack_h2(s[1][0], s[1][1]);
            uint32_t pa3 = pack_h2(s[1][2], s[1][3]);

            #pragma unroll
            for (int dt = 0; dt < 4; dt++) {
                const unsigned char* vb = Vs + (dt * 8 + gr) * 272 + m * 32 + 4 * tg;
                uint32_t b0 = *(const uint32_t*)(vb);
                uint32_t b1 = *(const uint32_t*)(vb + 16);
                mma16816(o[dt][0], o[dt][1], o[dt][2], o[dt][3],
                         pa0, pa1, pa2, pa3, b0, b1);
            }
        }
    }

    ls0 += __shfl_xor_sync(0xFFFFFFFFu, ls0, 1);
    ls0 += __shfl_xor_sync(0xFFFFFFFFu, ls0, 2);
    ls1 += __shfl_xor_sync(0xFFFFFFFFu, ls1, 1);
    ls1 += __shfl_xor_sync(0xFFFFFFFFu, ls1, 2);
    const float inv0 = 1.f / ls0;
    const float inv1 = 1.f / ls1;

    const int b = bh >> 5, area = (bh >> 3) & 3, h = bh & 7;
    const int nb = area * NA + i0;
    __half* outp = g_AOh + ((size_t)b * NPIX + nb) * CCH + h * HD;
    #pragma unroll
    for (int dt = 0; dt < 4; dt++) {
        *(__half2*)(outp + (size_t)(gr    ) * CCH + dt * 8 + 2 * tg) =
            __floats2half2_rn(o[dt][0] * inv0, o[dt][1] * inv0);
        *(__half2*)(outp + (size_t)(gr + 8) * CCH + dt * 8 + 2 * tg) =
            __floats2half2_rn(o[dt][2] * inv1, o[dt][3] * inv1);
    }
}

// ---------------------------------------------------------------------------
// proj_out via mma.sync: out[b,co,n] = Whp[co,:] . AOh[b,n,:] + shp[co]
// CTA 128co x 64n. AO tile [n][c] loads with non-trans ldmatrix.
// ---------------------------------------------------------------------------
__global__ __launch_bounds__(256) void proj_out_mma(float* __restrict__ out)
{
    __shared__ __align__(16) __half Ws[128][72];
    __shared__ __align__(16) __half As[64][72];

    const int b   = blockIdx.z;
    const int co0 = blockIdx.y * 128;
    const int n0  = blockIdx.x * 64;
    const int t    = threadIdx.x;
    const int lane = t & 31, wid = t >> 5;
    const int wo = wid >> 1, wn = wid & 1;
    const int gr = lane >> 2, tg = lane & 3;

    const __half* ab = g_AOh + (size_t)b * NPIX * CCH;

    float acc[2][4][4];
    #pragma unroll
    for (int i = 0; i < 2; i++)
        #pragma unroll
        for (int j = 0; j < 4; j++)
            #pragma unroll
            for (int k = 0; k < 4; k++) acc[i][j][k] = 0.f;

    for (int k0 = 0; k0 < 256; k0 += 64) {
        if (k0) __syncthreads();
        #pragma unroll
        for (int u = 0; u < 4; u++) {
            int idx = t + u * 256;
            int row = idx >> 3, seg = idx & 7;
            *(uint4*)&Ws[row][seg * 8] =
                *(const uint4*)(g_Whp + (size_t)(co0 + row) * 256 + k0 + seg * 8);
        }
        #pragma unroll
        for (int u = 0; u < 2; u++) {
            int idx = t + u * 256;
            int row = idx >> 3, seg = idx & 7;
            *(uint4*)&As[row][seg * 8] =
                *(const uint4*)(ab + (size_t)(n0 + row) * CCH + k0 + seg * 8);
        }
        __syncthreads();

        #pragma unroll
        for (int k16 = 0; k16 < 4; k16++) {
            uint32_t a[2][4];
            #pragma unroll
            for (int ot = 0; ot < 2; ot++) {
                uint32_t addr = cvta_sh(&Ws[wo * 32 + ot * 16 + (lane & 15)]
                                           [k16 * 16 + ((lane >> 4) << 3)]);
                LDMX4(a[ot][0], a[ot][1], a[ot][2], a[ot][3], addr);
            }
            uint32_t bf[2][4];
            #pragma unroll
            for (int nt = 0; nt < 2; nt++) {
                uint32_t addr = cvta_sh(&As[wn * 32 + nt * 16 + ((lane >> 4) << 3) + (lane & 7)]
                                           [k16 * 16 + (lane & 8)]);
                LDMX4(bf[nt][0], bf[nt][1], bf[nt][2], bf[nt][3], addr);
            }
            #pragma unroll
            for (int ot = 0; ot < 2; ot++)
                #pragma unroll
                for (int nt = 0; nt < 2; nt++)
                    #pragma unroll
                    for (int nh = 0; nh < 2; nh++) {
                        int ni = nt * 2 + nh;
                        mma16816(acc[ot][ni][0], acc[ot][ni][1], acc[ot][ni][2], acc[ot][ni][3],
                                 a[ot][0], a[ot][1], a[ot][2], a[ot][3],
                                 bf[nt][nh * 2], bf[nt][nh * 2 + 1]);
                    }
        }
    }

    #pragma unroll
    for (int ot = 0; ot < 2; ot++) {
        const int co = co0 + wo * 32 + ot * 16 + gr;
        const float sh0 = g_shp[co], sh1 = g_shp[co + 8];
        #pragma unroll
        for (int ni = 0; ni < 4; ni++) {
            int n = n0 + wn * 32 + (ni >> 1) * 16 + (ni & 1) * 8 + 2 * tg;
            float2 r0, r1;
            r0.x = acc[ot][ni][0] + sh0; r0.y = acc[ot][ni][1] + sh0;
            r1.x = acc[ot][ni][2] + sh1; r1.y = acc[ot][ni][3] + sh1;
            *(float2*)(out + ((size_t)(b * CCH + co    )) * NPIX + n) = r0;
            *(float2*)(out + ((size_t)(b * CCH + co + 8)) * NPIX + n) = r1;
        }
    }
}

// ---------------------------------------------------------------------------
extern "C" void kernel_launch(void* const* d_in, const int* in_sizes, int n_in,
                              void* d_out, int out_size)
{
    const float* x    = (const float*)d_in[0];
    const float* w_qk = (const float*)d_in[1];
    const float* g_qk = (const float*)d_in[2];
    const float* b_qk = (const float*)d_in[3];
    const float* m_qk = (const float*)d_in[4];
    const float* v_qk = (const float*)d_in[5];
    const float* w_v  = (const float*)d_in[6];
    const float* g_v  = (const float*)d_in[7];
    const float* b_v  = (const float*)d_in[8];
    const float* m_v  = (const float*)d_in[9];
    const float* v_v  = (const float*)d_in[10];
    const float* w_p  = (const float*)d_in[11];
    const float* g_p  = (const float*)d_in[12];
    const float* b_p  = (const float*)d_in[13];
    const float* m_p  = (const float*)d_in[14];
    const float* v_p  = (const float*)d_in[15];
    float* out = (float*)d_out;

    prep_w<<<1024, 256>>>(w_qk, g_qk, b_qk, m_qk, v_qk,
                          w_v,  g_v,  b_v,  m_v,  v_v,
                          w_p,  g_p,  b_p,  m_p,  v_p);
    prep_x<<<2048, 256>>>(x);
    proj_in_mma<<<dim3(64, 6, BATCH), 256>>>();
    attn_mma<<<dim3(8, 64), 256>>>();
    proj_out_mma<<<dim3(64, 2, BATCH), 256>>>(out);
}

// round 7
// speedup vs baseline: 6.7780x; 1.0868x over previous
#include <cuda_runtime.h>
#include <cuda_fp16.h>
#include <cstdint>

#define BATCH 2
#define CCH   256
#define NPIX  4096      // 64*64
#define BA    8         // BATCH*AREA
#define NA    1024      // NPIX/AREA
#define NH    8
#define HD    32
#define EPS   1e-5f

// scale * log2(e) folded into W_q rows so P = exp2(S - SHIFT)
#define QSCALE (0.17677669529663687f * 1.4426950408889634f)
#define ESHIFT 8.0f

// Scratch (device globals; no allocation allowed)
__device__ __half g_Qh[BA * NH * NA * HD];    // [bh][i][d]  pre-scaled fp16
__device__ __half g_Kh[BA * NH * NA * HD];    // [bh][j][d]  fp16
__device__ __half g_Vh[BA * NH * HD * NA];    // [bh][d][j]  TRANSPOSED fp16
__device__ __half g_AOh[BATCH * NPIX * CCH];  // [b][n][c]   fp16
__device__ __half g_xh[BATCH * CCH * NPIX];   // [b][c][n]   fp16
__device__ __half g_Wh[768 * 256];            // BN-folded w_qk (Q rows xQSCALE) + w_v
__device__ __half g_Whp[256 * 256];           // BN-folded w_p
__device__ float  g_sh[768];
__device__ float  g_shp[256];

// ---------------------------------------------------------------------------
// PTX helpers
// ---------------------------------------------------------------------------
__device__ __forceinline__ void mma16816(float& c0, float& c1, float& c2, float& c3,
                                         uint32_t a0, uint32_t a1, uint32_t a2, uint32_t a3,
                                         uint32_t b0, uint32_t b1)
{
    asm volatile(
        "mma.sync.aligned.m16n8k16.row.col.f32.f16.f16.f32 "
        "{%0,%1,%2,%3}, {%4,%5,%6,%7}, {%8,%9}, {%0,%1,%2,%3};"
        : "+f"(c0), "+f"(c1), "+f"(c2), "+f"(c3)
        : "r"(a0), "r"(a1), "r"(a2), "r"(a3), "r"(b0), "r"(b1));
}

__device__ __forceinline__ float ex2f(float x) {
    float r;
    asm("ex2.approx.ftz.f32 %0, %1;" : "=f"(r) : "f"(x));
    return r;
}

__device__ __forceinline__ uint32_t pack_h2(float lo, float hi) {
    uint32_t r;
    asm("cvt.rn.f16x2.f32 %0, %1, %2;" : "=r"(r) : "f"(hi), "f"(lo));
    return r;
}

__device__ __forceinline__ uint32_t cvta_sh(const void* p) {
    return (uint32_t)__cvta_generic_to_shared(p);
}

__device__ __forceinline__ void cp16(void* sm, const void* gm) {
    asm volatile("cp.async.cg.shared.global [%0], [%1], 16;"
        :: "r"(cvta_sh(sm)), "l"(gm));
}
#define CP_COMMIT() asm volatile("cp.async.commit_group;")
#define CP_WAIT(n)  asm volatile("cp.async.wait_group %0;" :: "n"(n))

#define LDMX4(r0,r1,r2,r3,addr) \
    asm volatile("ldmatrix.sync.aligned.m8n8.x4.shared.b16 {%0,%1,%2,%3}, [%4];" \
        : "=r"(r0),"=r"(r1),"=r"(r2),"=r"(r3) : "r"(addr))
#define LDMX4T(r0,r1,r2,r3,addr) \
    asm volatile("ldmatrix.sync.aligned.m8n8.x4.trans.shared.b16 {%0,%1,%2,%3}, [%4];" \
        : "=r"(r0),"=r"(r1),"=r"(r2),"=r"(r3) : "r"(addr))

// ---------------------------------------------------------------------------
// Prepass: fold BN into weights, convert to fp16; compute shift vectors.
// ---------------------------------------------------------------------------
__global__ void prep_w(
    const float* __restrict__ w_qk, const float* __restrict__ g_qk, const float* __restrict__ b_qk,
    const float* __restrict__ m_qk, const float* __restrict__ v_qk,
    const float* __restrict__ w_v,  const float* __restrict__ g_v,  const float* __restrict__ b_v,
    const float* __restrict__ m_v,  const float* __restrict__ v_v,
    const float* __restrict__ w_p,  const float* __restrict__ g_p,  const float* __restrict__ b_p,
    const float* __restrict__ m_p,  const float* __restrict__ v_p)
{
    const int row = blockIdx.x;
    const int c   = threadIdx.x;
    const float *w, *g, *b, *m, *v;
    __half* dst; float* shd;
    int r; float extra = 1.f;
    if (row < 512) {
        w = w_qk; g = g_qk; b = b_qk; m = m_qk; v = v_qk;
        r = row; dst = g_Wh + (size_t)row * 256; shd = g_sh + row;
        if (row < 256) extra = QSCALE;
    } else if (row < 768) {
        w = w_v; g = g_v; b = b_v; m = m_v; v = v_v;
        r = row - 512; dst = g_Wh + (size_t)row * 256; shd = g_sh + row;
    } else {
        w = w_p; g = g_p; b = b_p; m = m_p; v = v_p;
        r = row - 768; dst = g_Whp + (size_t)r * 256; shd = g_shp + r;
    }
    float s0 = g[r] * rsqrtf(v[r] + EPS);
    dst[c] = __float2half_rn(w[(size_t)r * 256 + c] * s0 * extra);
    if (c == 0) *shd = (b[r] - m[r] * s0) * extra;
}

__global__ void prep_x(const float* __restrict__ x)
{
    const int i = (blockIdx.x * 256 + threadIdx.x) * 4;
    float4 v = *(const float4*)(x + i);
    __half2* d = (__half2*)(g_xh + i);
    d[0] = __floats2half2_rn(v.x, v.y);
    d[1] = __floats2half2_rn(v.z, v.w);
}

// ---------------------------------------------------------------------------
// proj_in via mma.sync: Y[o,n] = Wh[o,:] . xh[b,:,n] + sh[o], o in [0,768)
// ---------------------------------------------------------------------------
__global__ __launch_bounds__(256) void proj_in_mma()
{
    __shared__ __align__(16) __half Ws[128][72];
    __shared__ __align__(16) __half Xs[64][72];

    const int b  = blockIdx.z;
    const int o0 = blockIdx.y * 128;
    const int n0 = blockIdx.x * 64;
    const int t    = threadIdx.x;
    const int lane = t & 31, wid = t >> 5;
    const int wo = wid >> 1, wn = wid & 1;
    const int gr = lane >> 2, tg = lane & 3;

    const __half* xb = g_xh + (size_t)b * CCH * NPIX;

    float acc[2][4][4];
    #pragma unroll
    for (int i = 0; i < 2; i++)
        #pragma unroll
        for (int j = 0; j < 4; j++)
            #pragma unroll
            for (int k = 0; k < 4; k++) acc[i][j][k] = 0.f;

    for (int k0 = 0; k0 < 256; k0 += 64) {
        if (k0) __syncthreads();
        #pragma unroll
        for (int u = 0; u < 4; u++) {
            int idx = t + u * 256;
            int row = idx >> 3, seg = idx & 7;
            *(uint4*)&Ws[row][seg * 8] =
                *(const uint4*)(g_Wh + (size_t)(o0 + row) * 256 + k0 + seg * 8);
        }
        #pragma unroll
        for (int u = 0; u < 2; u++) {
            int idx = t + u * 256;
            int row = idx >> 3, seg = idx & 7;
            *(uint4*)&Xs[row][seg * 8] =
                *(const uint4*)(xb + (size_t)(k0 + row) * NPIX + n0 + seg * 8);
        }
        __syncthreads();

        #pragma unroll
        for (int k16 = 0; k16 < 4; k16++) {
            uint32_t a[2][4];
            #pragma unroll
            for (int ot = 0; ot < 2; ot++) {
                uint32_t addr = cvta_sh(&Ws[wo * 32 + ot * 16 + (lane & 15)]
                                           [k16 * 16 + ((lane >> 4) << 3)]);
                LDMX4(a[ot][0], a[ot][1], a[ot][2], a[ot][3], addr);
            }
            uint32_t bf[2][4];
            #pragma unroll
            for (int nt = 0; nt < 2; nt++) {
                uint32_t addr = cvta_sh(&Xs[k16 * 16 + (lane & 15)]
                                           [wn * 32 + nt * 16 + ((lane >> 4) << 3)]);
                LDMX4T(bf[nt][0], bf[nt][1], bf[nt][2], bf[nt][3], addr);
            }
            #pragma unroll
            for (int ot = 0; ot < 2; ot++)
                #pragma unroll
                for (int nt = 0; nt < 2; nt++)
                    #pragma unroll
                    for (int nh = 0; nh < 2; nh++) {
                        int ni = nt * 2 + nh;
                        mma16816(acc[ot][ni][0], acc[ot][ni][1], acc[ot][ni][2], acc[ot][ni][3],
                                 a[ot][0], a[ot][1], a[ot][2], a[ot][3],
                                 bf[nt][nh * 2], bf[nt][nh * 2 + 1]);
                    }
        }
    }

    #pragma unroll
    for (int ot = 0; ot < 2; ot++) {
        const int og = o0 + wo * 32 + ot * 16 + gr;
        const float sh0 = g_sh[og], sh1 = g_sh[og + 8];
        if (o0 < 512) {
            __half* dst = (o0 < 256) ? g_Qh : g_Kh;
            const int ob0 = og & 255, ob1 = (og + 8) & 255;
            const int h0 = ob0 >> 5, d0 = ob0 & 31;
            const int h1 = ob1 >> 5, d1 = ob1 & 31;
            #pragma unroll
            for (int ni = 0; ni < 4; ni++) {
                int n  = n0 + wn * 32 + (ni >> 1) * 16 + (ni & 1) * 8 + 2 * tg;
                int ba = b * 4 + (n >> 10), na = n & 1023;
                size_t base = (size_t)(ba * NH) * NA * HD;
                dst[base + ((size_t)h0 * NA + na    ) * HD + d0] = __float2half_rn(acc[ot][ni][0] + sh0);
                dst[base + ((size_t)h0 * NA + na + 1) * HD + d0] = __float2half_rn(acc[ot][ni][1] + sh0);
                dst[base + ((size_t)h1 * NA + na    ) * HD + d1] = __float2half_rn(acc[ot][ni][2] + sh1);
                dst[base + ((size_t)h1 * NA + na + 1) * HD + d1] = __float2half_rn(acc[ot][ni][3] + sh1);
            }
        } else {
            const int oc0 = og - 512, oc1 = og - 512 + 8;
            const int h0 = oc0 >> 5, d0 = oc0 & 31;
            const int h1 = oc1 >> 5, d1 = oc1 & 31;
            #pragma unroll
            for (int ni = 0; ni < 4; ni++) {
                int n  = n0 + wn * 32 + (ni >> 1) * 16 + (ni & 1) * 8 + 2 * tg;
                int ba = b * 4 + (n >> 10), na = n & 1023;
                *(__half2*)&g_Vh[(((size_t)(ba * NH + h0)) * HD + d0) * NA + na] =
                    __floats2half2_rn(acc[ot][ni][0] + sh0, acc[ot][ni][1] + sh0);
                *(__half2*)&g_Vh[(((size_t)(ba * NH + h1)) * HD + d1) * NA + na] =
                    __floats2half2_rn(acc[ot][ni][2] + sh1, acc[ot][ni][3] + sh1);
            }
        }
    }
}

// ---------------------------------------------------------------------------
// Attention v2: 32 q rows/warp, ldmatrix fragment loads, cp.async double buffer.
// Grid (4, 64), 256 threads = 8 warps. Warp covers q rows i0..i0+31.
// ---------------------------------------------------------------------------
__global__ __launch_bounds__(256) void attn_mma()
{
    __shared__ __align__(16) unsigned char Ks[2][128 * 80];   // [j][d] pitch 80
    __shared__ __align__(16) unsigned char Vs[2][32 * 272];   // [d][j] pitch 272

    const int t    = threadIdx.x;
    const int wid  = t >> 5;
    const int lane = t & 31;
    const int gr   = lane >> 2;
    const int tg   = lane & 3;
    const int bh   = blockIdx.y;
    const int q0   = blockIdx.x * 256;
    const int i0   = q0 + wid * 32;

    const __half* Qg = g_Qh + ((size_t)bh * NA + i0) * HD;
    const __half* Kg = g_Kh + (size_t)bh * NA * HD;
    const __half* Vg = g_Vh + (size_t)bh * HD * NA;

    // Q A-fragments: 2 m-tiles x 2 k-tiles
    uint32_t qa[2][2][4];
    #pragma unroll
    for (int mt = 0; mt < 2; mt++)
        #pragma unroll
        for (int kt = 0; kt < 2; kt++) {
            qa[mt][kt][0] = *(const uint32_t*)(Qg + (mt * 16 + gr    ) * HD + kt * 16 + 2 * tg    );
            qa[mt][kt][1] = *(const uint32_t*)(Qg + (mt * 16 + gr + 8) * HD + kt * 16 + 2 * tg    );
            qa[mt][kt][2] = *(const uint32_t*)(Qg + (mt * 16 + gr    ) * HD + kt * 16 + 2 * tg + 8);
            qa[mt][kt][3] = *(const uint32_t*)(Qg + (mt * 16 + gr + 8) * HD + kt * 16 + 2 * tg + 8);
        }

    float o[2][4][4];
    #pragma unroll
    for (int mt = 0; mt < 2; mt++)
        #pragma unroll
        for (int dt = 0; dt < 4; dt++)
            #pragma unroll
            for (int c = 0; c < 4; c++) o[mt][dt][c] = 0.f;
    float ls[2][2] = {{0.f, 0.f}, {0.f, 0.f}};

    // stage tile 0 into buf 0
    {
        #pragma unroll
        for (int u = 0; u < 2; u++) {
            int idx = t + u * 256;
            int row = idx >> 2, part = idx & 3;
            cp16(&Ks[0][row * 80 + part * 16], Kg + (size_t)row * HD + part * 8);
        }
        #pragma unroll
        for (int u = 0; u < 2; u++) {
            int idx = t + u * 256;
            int row = idx >> 4, part = idx & 15;
            cp16(&Vs[0][row * 272 + part * 16], Vg + (size_t)row * NA + part * 8);
        }
        CP_COMMIT();
    }

    #pragma unroll 1
    for (int it = 0; it < 8; it++) {
        const int buf = it & 1;
        if (it < 7) {
            const int j0 = (it + 1) * 128, nb = buf ^ 1;
            #pragma unroll
            for (int u = 0; u < 2; u++) {
                int idx = t + u * 256;
                int row = idx >> 2, part = idx & 3;
                cp16(&Ks[nb][row * 80 + part * 16], Kg + (size_t)(j0 + row) * HD + part * 8);
            }
            #pragma unroll
            for (int u = 0; u < 2; u++) {
                int idx = t + u * 256;
                int row = idx >> 4, part = idx & 15;
                cp16(&Vs[nb][row * 272 + part * 16], Vg + (size_t)row * NA + j0 + part * 8);
            }
            CP_COMMIT();
            CP_WAIT(1);
        } else {
            CP_WAIT(0);
        }
        __syncthreads();

        #pragma unroll
        for (int m = 0; m < 8; m++) {
            // K fragments: 2 ldmatrix.x4 -> kf[nt][b0k0,b1k0,b0k1,b1k1]
            uint32_t kf[2][4];
            {
                uint32_t a0 = cvta_sh(&Ks[buf][(m * 16 + (lane & 7)) * 80 + (lane >> 3) * 16]);
                LDMX4(kf[0][0], kf[0][1], kf[0][2], kf[0][3], a0);
                LDMX4(kf[1][0], kf[1][1], kf[1][2], kf[1][3], a0 + 8 * 80);
            }

            // S = Q.K^T for 2 m-tiles x 2 n-halves
            float s[2][2][4];
            #pragma unroll
            for (int mt = 0; mt < 2; mt++)
                #pragma unroll
                for (int h = 0; h < 2; h++) {
                    float c0 = 0.f, c1 = 0.f, c2 = 0.f, c3 = 0.f;
                    mma16816(c0, c1, c2, c3,
                             qa[mt][0][0], qa[mt][0][1], qa[mt][0][2], qa[mt][0][3],
                             kf[h][0], kf[h][1]);
                    mma16816(c0, c1, c2, c3,
                             qa[mt][1][0], qa[mt][1][1], qa[mt][1][2], qa[mt][1][3],
                             kf[h][2], kf[h][3]);
                    s[mt][h][0] = c0; s[mt][h][1] = c1; s[mt][h][2] = c2; s[mt][h][3] = c3;
                }

            // softmax numerator + row sums + pack P
            uint32_t pa[2][4];
            #pragma unroll
            for (int mt = 0; mt < 2; mt++) {
                #pragma unroll
                for (int h = 0; h < 2; h++)
                    #pragma unroll
                    for (int c = 0; c < 4; c++)
                        s[mt][h][c] = ex2f(s[mt][h][c] - ESHIFT);
                ls[mt][0] += s[mt][0][0] + s[mt][0][1] + s[mt][1][0] + s[mt][1][1];
                ls[mt][1] += s[mt][0][2] + s[mt][0][3] + s[mt][1][2] + s[mt][1][3];
                pa[mt][0] = pack_h2(s[mt][0][0], s[mt][0][1]);
                pa[mt][1] = pack_h2(s[mt][0][2], s[mt][0][3]);
                pa[mt][2] = pack_h2(s[mt][1][0], s[mt][1][1]);
                pa[mt][3] = pack_h2(s[mt][1][2], s[mt][1][3]);
            }

            // V fragments: 2 ldmatrix.x4 -> vf[dt][b0,b1]
            uint32_t vf[4][2];
            {
                uint32_t a0 = cvta_sh(&Vs[buf][(((lane >> 4) << 3) + (lane & 7)) * 272
                                               + m * 32 + ((lane >> 3) & 1) * 16]);
                LDMX4(vf[0][0], vf[0][1], vf[1][0], vf[1][1], a0);
                LDMX4(vf[2][0], vf[2][1], vf[3][0], vf[3][1], a0 + 16 * 272);
            }

            // O += P.V
            #pragma unroll
            for (int mt = 0; mt < 2; mt++)
                #pragma unroll
                for (int dt = 0; dt < 4; dt++)
                    mma16816(o[mt][dt][0], o[mt][dt][1], o[mt][dt][2], o[mt][dt][3],
                             pa[mt][0], pa[mt][1], pa[mt][2], pa[mt][3],
                             vf[dt][0], vf[dt][1]);
        }
        __syncthreads();
    }

    // ---- normalize + write AO[b][n][c] fp16 ----
    #pragma unroll
    for (int mt = 0; mt < 2; mt++) {
        #pragma unroll
        for (int r = 0; r < 2; r++) {
            ls[mt][r] += __shfl_xor_sync(0xFFFFFFFFu, ls[mt][r], 1);
            ls[mt][r] += __shfl_xor_sync(0xFFFFFFFFu, ls[mt][r], 2);
        }
    }

    const int b = bh >> 5, area = (bh >> 3) & 3, h = bh & 7;
    #pragma unroll
    for (int mt = 0; mt < 2; mt++) {
        const float inv0 = 1.f / ls[mt][0];
        const float inv1 = 1.f / ls[mt][1];
        const int nb = area * NA + i0 + mt * 16;
        __half* outp = g_AOh + ((size_t)b * NPIX + nb) * CCH + h * HD;
        #pragma unroll
        for (int dt = 0; dt < 4; dt++) {
            *(__half2*)(outp + (size_t)(gr    ) * CCH + dt * 8 + 2 * tg) =
                __floats2half2_rn(o[mt][dt][0] * inv0, o[mt][dt][1] * inv0);
            *(__half2*)(outp + (size_t)(gr + 8) * CCH + dt * 8 + 2 * tg) =
                __floats2half2_rn(o[mt][dt][2] * inv1, o[mt][dt][3] * inv1);
        }
    }
}

// ---------------------------------------------------------------------------
// proj_out via mma.sync: out[b,co,n] = Whp[co,:] . AOh[b,n,:] + shp[co]
// ---------------------------------------------------------------------------
__global__ __launch_bounds__(256) void proj_out_mma(float* __restrict__ out)
{
    __shared__ __align__(16) __half Ws[128][72];
    __shared__ __align__(16) __half As[64][72];

    const int b   = blockIdx.z;
    const int co0 = blockIdx.y * 128;
    const int n0  = blockIdx.x * 64;
    const int t    = threadIdx.x;
    const int lane = t & 31, wid = t >> 5;
    const int wo = wid >> 1, wn = wid & 1;
    const int gr = lane >> 2, tg = lane & 3;

    const __half* ab = g_AOh + (size_t)b * NPIX * CCH;

    float acc[2][4][4];
    #pragma unroll
    for (int i = 0; i < 2; i++)
        #pragma unroll
        for (int j = 0; j < 4; j++)
            #pragma unroll
            for (int k = 0; k < 4; k++) acc[i][j][k] = 0.f;

    for (int k0 = 0; k0 < 256; k0 += 64) {
        if (k0) __syncthreads();
        #pragma unroll
        for (int u = 0; u < 4; u++) {
            int idx = t + u * 256;
            int row = idx >> 3, seg = idx & 7;
            *(uint4*)&Ws[row][seg * 8] =
                *(const uint4*)(g_Whp + (size_t)(co0 + row) * 256 + k0 + seg * 8);
        }
        #pragma unroll
        for (int u = 0; u < 2; u++) {
            int idx = t + u * 256;
            int row = idx >> 3, seg = idx & 7;
            *(uint4*)&As[row][seg * 8] =
                *(const uint4*)(ab + (size_t)(n0 + row) * CCH + k0 + seg * 8);
        }
        __syncthreads();

        #pragma unroll
        for (int k16 = 0; k16 < 4; k16++) {
            uint32_t a[2][4];
            #pragma unroll
            for (int ot = 0; ot < 2; ot++) {
                uint32_t addr = cvta_sh(&Ws[wo * 32 + ot * 16 + (lane & 15)]
                                           [k16 * 16 + ((lane >> 4) << 3)]);
                LDMX4(a[ot][0], a[ot][1], a[ot][2], a[ot][3], addr);
            }
            uint32_t bf[2][4];
            #pragma unroll
            for (int nt = 0; nt < 2; nt++) {
                uint32_t addr = cvta_sh(&As[wn * 32 + nt * 16 + ((lane >> 4) << 3) + (lane & 7)]
                                           [k16 * 16 + (lane & 8)]);
                LDMX4(bf[nt][0], bf[nt][1], bf[nt][2], bf[nt][3], addr);
            }
            #pragma unroll
            for (int ot = 0; ot < 2; ot++)
                #pragma unroll
                for (int nt = 0; nt < 2; nt++)
                    #pragma unroll
                    for (int nh = 0; nh < 2; nh++) {
                        int ni = nt * 2 + nh;
                        mma16816(acc[ot][ni][0], acc[ot][ni][1], acc[ot][ni][2], acc[ot][ni][3],
                                 a[ot][0], a[ot][1], a[ot][2], a[ot][3],
                                 bf[nt][nh * 2], bf[nt][nh * 2 + 1]);
                    }
        }
    }

    #pragma unroll
    for (int ot = 0; ot < 2; ot++) {
        const int co = co0 + wo * 32 + ot * 16 + gr;
        const float sh0 = g_shp[co], sh1 = g_shp[co + 8];
        #pragma unroll
        for (int ni = 0; ni < 4; ni++) {
            int n = n0 + wn * 32 + (ni >> 1) * 16 + (ni & 1) * 8 + 2 * tg;
            float2 r0, r1;
            r0.x = acc[ot][ni][0] + sh0; r0.y = acc[ot][ni][1] + sh0;
            r1.x = acc[ot][ni][2] + sh1; r1.y = acc[ot][ni][3] + sh1;
            *(float2*)(out + ((size_t)(b * CCH + co    )) * NPIX + n) = r0;
            *(float2*)(out + ((size_t)(b * CCH + co + 8)) * NPIX + n) = r1;
        }
    }
}

// ---------------------------------------------------------------------------
extern "C" void kernel_launch(void* const* d_in, const int* in_sizes, int n_in,
                              void* d_out, int out_size)
{
    const float* x    = (const float*)d_in[0];
    const float* w_qk = (const float*)d_in[1];
    const float* g_qk = (const float*)d_in[2];
    const float* b_qk = (const float*)d_in[3];
    const float* m_qk = (const float*)d_in[4];
    const float* v_qk = (const float*)d_in[5];
    const float* w_v  = (const float*)d_in[6];
    const float* g_v  = (const float*)d_in[7];
    const float* b_v  = (const float*)d_in[8];
    const float* m_v  = (const float*)d_in[9];
    const float* v_v  = (const float*)d_in[10];
    const float* w_p  = (const float*)d_in[11];
    const float* g_p  = (const float*)d_in[12];
    const float* b_p  = (const float*)d_in[13];
    const float* m_p  = (const float*)d_in[14];
    const float* v_p  = (const float*)d_in[15];
    float* out = (float*)d_out;

    prep_w<<<1024, 256>>>(w_qk, g_qk, b_qk, m_qk, v_qk,
                          w_v,  g_v,  b_v,  m_v,  v_v,
                          w_p,  g_p,  b_p,  m_p,  v_p);
    prep_x<<<2048, 256>>>(x);
    proj_in_mma<<<dim3(64, 6, BATCH), 256>>>();
    attn_mma<<<dim3(4, 64), 256>>>();
    proj_out_mma<<<dim3(64, 2, BATCH), 256>>>(out);
}

// round 8
// speedup vs baseline: 6.9950x; 1.0320x over previous
#include <cuda_runtime.h>
#include <cuda_fp16.h>
#include <cstdint>

#define BATCH 2
#define CCH   256
#define NPIX  4096      // 64*64
#define BA    8         // BATCH*AREA
#define NA    1024      // NPIX/AREA
#define NH    8
#define HD    32
#define EPS   1e-5f

// scale * log2(e) folded into W_q rows so P = exp2(S - SHIFT)
#define QSCALE (0.17677669529663687f * 1.4426950408889634f)
#define ESHIFT 8.0f
#define H2ONES 0x3C003C00u

// Scratch (device globals; no allocation allowed)
__device__ __half g_Qh[BA * NH * NA * HD];    // [bh][i][d]  pre-scaled fp16
__device__ __half g_Kh[BA * NH * NA * HD];    // [bh][j][d]  fp16
__device__ __half g_Vh[BA * NH * HD * NA];    // [bh][d][j]  TRANSPOSED fp16
__device__ __half g_AOh[BATCH * NPIX * CCH];  // [b][n][c]   fp16
__device__ __half g_xh[BATCH * CCH * NPIX];   // [b][c][n]   fp16
__device__ __half g_Wh[768 * 256];            // BN-folded w_qk (Q rows xQSCALE) + w_v
__device__ __half g_Whp[256 * 256];           // BN-folded w_p
__device__ float  g_sh[768];
__device__ float  g_shp[256];

// ---------------------------------------------------------------------------
// PTX helpers
// ---------------------------------------------------------------------------
__device__ __forceinline__ void mma16816(float& c0, float& c1, float& c2, float& c3,
                                         uint32_t a0, uint32_t a1, uint32_t a2, uint32_t a3,
                                         uint32_t b0, uint32_t b1)
{
    asm volatile(
        "mma.sync.aligned.m16n8k16.row.col.f32.f16.f16.f32 "
        "{%0,%1,%2,%3}, {%4,%5,%6,%7}, {%8,%9}, {%0,%1,%2,%3};"
        : "+f"(c0), "+f"(c1), "+f"(c2), "+f"(c3)
        : "r"(a0), "r"(a1), "r"(a2), "r"(a3), "r"(b0), "r"(b1));
}

__device__ __forceinline__ uint32_t pack_h2(float lo, float hi) {
    uint32_t r;
    asm("cvt.rn.f16x2.f32 %0, %1, %2;" : "=r"(r) : "f"(hi), "f"(lo));
    return r;
}

// two exp2 in one MUFU op, result stays packed fp16x2
__device__ __forceinline__ uint32_t h2ex2(uint32_t x) {
    uint32_t r;
    asm("ex2.approx.f16x2 %0, %1;" : "=r"(r) : "r"(x));
    return r;
}

__device__ __forceinline__ uint32_t cvta_sh(const void* p) {
    return (uint32_t)__cvta_generic_to_shared(p);
}

__device__ __forceinline__ void cp16(void* sm, const void* gm) {
    asm volatile("cp.async.cg.shared.global [%0], [%1], 16;"
        :: "r"(cvta_sh(sm)), "l"(gm));
}
#define CP_COMMIT() asm volatile("cp.async.commit_group;")
#define CP_WAIT(n)  asm volatile("cp.async.wait_group %0;" :: "n"(n))

#define LDMX4(r0,r1,r2,r3,addr) \
    asm volatile("ldmatrix.sync.aligned.m8n8.x4.shared.b16 {%0,%1,%2,%3}, [%4];" \
        : "=r"(r0),"=r"(r1),"=r"(r2),"=r"(r3) : "r"(addr))
#define LDMX4T(r0,r1,r2,r3,addr) \
    asm volatile("ldmatrix.sync.aligned.m8n8.x4.trans.shared.b16 {%0,%1,%2,%3}, [%4];" \
        : "=r"(r0),"=r"(r1),"=r"(r2),"=r"(r3) : "r"(addr))

// ---------------------------------------------------------------------------
// Prepass: fold BN into weights, convert to fp16; compute shift vectors.
// ---------------------------------------------------------------------------
__global__ void prep_w(
    const float* __restrict__ w_qk, const float* __restrict__ g_qk, const float* __restrict__ b_qk,
    const float* __restrict__ m_qk, const float* __restrict__ v_qk,
    const float* __restrict__ w_v,  const float* __restrict__ g_v,  const float* __restrict__ b_v,
    const float* __restrict__ m_v,  const float* __restrict__ v_v,
    const float* __restrict__ w_p,  const float* __restrict__ g_p,  const float* __restrict__ b_p,
    const float* __restrict__ m_p,  const float* __restrict__ v_p)
{
    const int row = blockIdx.x;
    const int c   = threadIdx.x;
    const float *w, *g, *b, *m, *v;
    __half* dst; float* shd;
    int r; float extra = 1.f;
    if (row < 512) {
        w = w_qk; g = g_qk; b = b_qk; m = m_qk; v = v_qk;
        r = row; dst = g_Wh + (size_t)row * 256; shd = g_sh + row;
        if (row < 256) extra = QSCALE;
    } else if (row < 768) {
        w = w_v; g = g_v; b = b_v; m = m_v; v = v_v;
        r = row - 512; dst = g_Wh + (size_t)row * 256; shd = g_sh + row;
    } else {
        w = w_p; g = g_p; b = b_p; m = m_p; v = v_p;
        r = row - 768; dst = g_Whp + (size_t)r * 256; shd = g_shp + r;
    }
    float s0 = g[r] * rsqrtf(v[r] + EPS);
    dst[c] = __float2half_rn(w[(size_t)r * 256 + c] * s0 * extra);
    if (c == 0) *shd = (b[r] - m[r] * s0) * extra;
}

__global__ void prep_x(const float* __restrict__ x)
{
    const int i = (blockIdx.x * 256 + threadIdx.x) * 4;
    float4 v = *(const float4*)(x + i);
    __half2* d = (__half2*)(g_xh + i);
    d[0] = __floats2half2_rn(v.x, v.y);
    d[1] = __floats2half2_rn(v.z, v.w);
}

// ---------------------------------------------------------------------------
// proj_in via mma.sync: Y[o,n] = Wh[o,:] . xh[b,:,n] + sh[o], o in [0,768)
// ---------------------------------------------------------------------------
__global__ __launch_bounds__(256) void proj_in_mma()
{
    __shared__ __align__(16) __half Ws[128][72];
    __shared__ __align__(16) __half Xs[64][72];

    const int b  = blockIdx.z;
    const int o0 = blockIdx.y * 128;
    const int n0 = blockIdx.x * 64;
    const int t    = threadIdx.x;
    const int lane = t & 31, wid = t >> 5;
    const int wo = wid >> 1, wn = wid & 1;
    const int gr = lane >> 2, tg = lane & 3;

    const __half* xb = g_xh + (size_t)b * CCH * NPIX;

    float acc[2][4][4];
    #pragma unroll
    for (int i = 0; i < 2; i++)
        #pragma unroll
        for (int j = 0; j < 4; j++)
            #pragma unroll
            for (int k = 0; k < 4; k++) acc[i][j][k] = 0.f;

    for (int k0 = 0; k0 < 256; k0 += 64) {
        if (k0) __syncthreads();
        #pragma unroll
        for (int u = 0; u < 4; u++) {
            int idx = t + u * 256;
            int row = idx >> 3, seg = idx & 7;
            *(uint4*)&Ws[row][seg * 8] =
                *(const uint4*)(g_Wh + (size_t)(o0 + row) * 256 + k0 + seg * 8);
        }
        #pragma unroll
        for (int u = 0; u < 2; u++) {
            int idx = t + u * 256;
            int row = idx >> 3, seg = idx & 7;
            *(uint4*)&Xs[row][seg * 8] =
                *(const uint4*)(xb + (size_t)(k0 + row) * NPIX + n0 + seg * 8);
        }
        __syncthreads();

        #pragma unroll
        for (int k16 = 0; k16 < 4; k16++) {
            uint32_t a[2][4];
            #pragma unroll
            for (int ot = 0; ot < 2; ot++) {
                uint32_t addr = cvta_sh(&Ws[wo * 32 + ot * 16 + (lane & 15)]
                                           [k16 * 16 + ((lane >> 4) << 3)]);
                LDMX4(a[ot][0], a[ot][1], a[ot][2], a[ot][3], addr);
            }
            uint32_t bf[2][4];
            #pragma unroll
            for (int nt = 0; nt < 2; nt++) {
                uint32_t addr = cvta_sh(&Xs[k16 * 16 + (lane & 15)]
                                           [wn * 32 + nt * 16 + ((lane >> 4) << 3)]);
                LDMX4T(bf[nt][0], bf[nt][1], bf[nt][2], bf[nt][3], addr);
            }
            #pragma unroll
            for (int ot = 0; ot < 2; ot++)
                #pragma unroll
                for (int nt = 0; nt < 2; nt++)
                    #pragma unroll
                    for (int nh = 0; nh < 2; nh++) {
                        int ni = nt * 2 + nh;
                        mma16816(acc[ot][ni][0], acc[ot][ni][1], acc[ot][ni][2], acc[ot][ni][3],
                                 a[ot][0], a[ot][1], a[ot][2], a[ot][3],
                                 bf[nt][nh * 2], bf[nt][nh * 2 + 1]);
                    }
        }
    }

    #pragma unroll
    for (int ot = 0; ot < 2; ot++) {
        const int og = o0 + wo * 32 + ot * 16 + gr;
        const float sh0 = g_sh[og], sh1 = g_sh[og + 8];
        if (o0 < 512) {
            __half* dst = (o0 < 256) ? g_Qh : g_Kh;
            const int ob0 = og & 255, ob1 = (og + 8) & 255;
            const int h0 = ob0 >> 5, d0 = ob0 & 31;
            const int h1 = ob1 >> 5, d1 = ob1 & 31;
            #pragma unroll
            for (int ni = 0; ni < 4; ni++) {
                int n  = n0 + wn * 32 + (ni >> 1) * 16 + (ni & 1) * 8 + 2 * tg;
                int ba = b * 4 + (n >> 10), na = n & 1023;
                size_t base = (size_t)(ba * NH) * NA * HD;
                dst[base + ((size_t)h0 * NA + na    ) * HD + d0] = __float2half_rn(acc[ot][ni][0] + sh0);
                dst[base + ((size_t)h0 * NA + na + 1) * HD + d0] = __float2half_rn(acc[ot][ni][1] + sh0);
                dst[base + ((size_t)h1 * NA + na    ) * HD + d1] = __float2half_rn(acc[ot][ni][2] + sh1);
                dst[base + ((size_t)h1 * NA + na + 1) * HD + d1] = __float2half_rn(acc[ot][ni][3] + sh1);
            }
        } else {
            const int oc0 = og - 512, oc1 = og - 512 + 8;
            const int h0 = oc0 >> 5, d0 = oc0 & 31;
            const int h1 = oc1 >> 5, d1 = oc1 & 31;
            #pragma unroll
            for (int ni = 0; ni < 4; ni++) {
                int n  = n0 + wn * 32 + (ni >> 1) * 16 + (ni & 1) * 8 + 2 * tg;
                int ba = b * 4 + (n >> 10), na = n & 1023;
                *(__half2*)&g_Vh[(((size_t)(ba * NH + h0)) * HD + d0) * NA + na] =
                    __floats2half2_rn(acc[ot][ni][0] + sh0, acc[ot][ni][1] + sh0);
                *(__half2*)&g_Vh[(((size_t)(ba * NH + h1)) * HD + d1) * NA + na] =
                    __floats2half2_rn(acc[ot][ni][2] + sh1, acc[ot][ni][3] + sh1);
            }
        }
    }
}

// ---------------------------------------------------------------------------
// Attention v3: 32 q rows/warp, ldmatrix frags, cp.async double buffer,
// shift folded into S accumulator init, f16x2 exp2, row sums via ones-MMA.
// Grid (4, 64), 256 threads = 8 warps.
// ---------------------------------------------------------------------------
__global__ __launch_bounds__(256) void attn_mma()
{
    __shared__ __align__(16) unsigned char Ks[2][128 * 80];   // [j][d] pitch 80
    __shared__ __align__(16) unsigned char Vs[2][32 * 272];   // [d][j] pitch 272

    const int t    = threadIdx.x;
    const int wid  = t >> 5;
    const int lane = t & 31;
    const int gr   = lane >> 2;
    const int tg   = lane & 3;
    const int bh   = blockIdx.y;
    const int q0   = blockIdx.x * 256;
    const int i0   = q0 + wid * 32;

    const __half* Qg = g_Qh + ((size_t)bh * NA + i0) * HD;
    const __half* Kg = g_Kh + (size_t)bh * NA * HD;
    const __half* Vg = g_Vh + (size_t)bh * HD * NA;

    // Q A-fragments: 2 m-tiles x 2 k-tiles
    uint32_t qa[2][2][4];
    #pragma unroll
    for (int mt = 0; mt < 2; mt++)
        #pragma unroll
        for (int kt = 0; kt < 2; kt++) {
            qa[mt][kt][0] = *(const uint32_t*)(Qg + (mt * 16 + gr    ) * HD + kt * 16 + 2 * tg    );
            qa[mt][kt][1] = *(const uint32_t*)(Qg + (mt * 16 + gr + 8) * HD + kt * 16 + 2 * tg    );
            qa[mt][kt][2] = *(const uint32_t*)(Qg + (mt * 16 + gr    ) * HD + kt * 16 + 2 * tg + 8);
            qa[mt][kt][3] = *(const uint32_t*)(Qg + (mt * 16 + gr + 8) * HD + kt * 16 + 2 * tg + 8);
        }

    float o[2][4][4];
    #pragma unroll
    for (int mt = 0; mt < 2; mt++)
        #pragma unroll
        for (int dt = 0; dt < 4; dt++)
            #pragma unroll
            for (int c = 0; c < 4; c++) o[mt][dt][c] = 0.f;
    // row-sum accumulators via ones-MMA: lacc[mt][0] = row gr, lacc[mt][2] = row gr+8
    float lacc[2][4];
    #pragma unroll
    for (int mt = 0; mt < 2; mt++)
        #pragma unroll
        for (int c = 0; c < 4; c++) lacc[mt][c] = 0.f;

    // stage tile 0 into buf 0
    {
        #pragma unroll
        for (int u = 0; u < 2; u++) {
            int idx = t + u * 256;
            int row = idx >> 2, part = idx & 3;
            cp16(&Ks[0][row * 80 + part * 16], Kg + (size_t)row * HD + part * 8);
        }
        #pragma unroll
        for (int u = 0; u < 2; u++) {
            int idx = t + u * 256;
            int row = idx >> 4, part = idx & 15;
            cp16(&Vs[0][row * 272 + part * 16], Vg + (size_t)row * NA + part * 8);
        }
        CP_COMMIT();
    }

    #pragma unroll 1
    for (int it = 0; it < 8; it++) {
        const int buf = it & 1;
        if (it < 7) {
            const int j0 = (it + 1) * 128, nb = buf ^ 1;
            #pragma unroll
            for (int u = 0; u < 2; u++) {
                int idx = t + u * 256;
                int row = idx >> 2, part = idx & 3;
                cp16(&Ks[nb][row * 80 + part * 16], Kg + (size_t)(j0 + row) * HD + part * 8);
            }
            #pragma unroll
            for (int u = 0; u < 2; u++) {
                int idx = t + u * 256;
                int row = idx >> 4, part = idx & 15;
                cp16(&Vs[nb][row * 272 + part * 16], Vg + (size_t)row * NA + j0 + part * 8);
            }
            CP_COMMIT();
            CP_WAIT(1);
        } else {
            CP_WAIT(0);
        }
        __syncthreads();

        #pragma unroll
        for (int m = 0; m < 8; m++) {
            // K fragments: 2 ldmatrix.x4
            uint32_t kf[2][4];
            {
                uint32_t a0 = cvta_sh(&Ks[buf][(m * 16 + (lane & 7)) * 80 + (lane >> 3) * 16]);
                LDMX4(kf[0][0], kf[0][1], kf[0][2], kf[0][3], a0);
                LDMX4(kf[1][0], kf[1][1], kf[1][2], kf[1][3], a0 + 8 * 80);
            }

            // S = Q.K^T - ESHIFT (shift folded into accumulator init)
            float s[2][2][4];
            #pragma unroll
            for (int mt = 0; mt < 2; mt++)
                #pragma unroll
                for (int h = 0; h < 2; h++) {
                    float c0 = -ESHIFT, c1 = -ESHIFT, c2 = -ESHIFT, c3 = -ESHIFT;
                    mma16816(c0, c1, c2, c3,
                             qa[mt][0][0], qa[mt][0][1], qa[mt][0][2], qa[mt][0][3],
                             kf[h][0], kf[h][1]);
                    mma16816(c0, c1, c2, c3,
                             qa[mt][1][0], qa[mt][1][1], qa[mt][1][2], qa[mt][1][3],
                             kf[h][2], kf[h][3]);
                    s[mt][h][0] = c0; s[mt][h][1] = c1; s[mt][h][2] = c2; s[mt][h][3] = c3;
                }

            // pack then f16x2 exp2 -> P fragments directly
            uint32_t pa[2][4];
            #pragma unroll
            for (int mt = 0; mt < 2; mt++) {
                pa[mt][0] = h2ex2(pack_h2(s[mt][0][0], s[mt][0][1]));
                pa[mt][1] = h2ex2(pack_h2(s[mt][0][2], s[mt][0][3]));
                pa[mt][2] = h2ex2(pack_h2(s[mt][1][0], s[mt][1][1]));
                pa[mt][3] = h2ex2(pack_h2(s[mt][1][2], s[mt][1][3]));
            }

            // row sums: lacc += P . ones  (tensor pipe, no scalar adds)
            #pragma unroll
            for (int mt = 0; mt < 2; mt++)
                mma16816(lacc[mt][0], lacc[mt][1], lacc[mt][2], lacc[mt][3],
                         pa[mt][0], pa[mt][1], pa[mt][2], pa[mt][3],
                         H2ONES, H2ONES);

            // V fragments: 2 ldmatrix.x4
            uint32_t vf[4][2];
            {
                uint32_t a0 = cvta_sh(&Vs[buf][(((lane >> 4) << 3) + (lane & 7)) * 272
                                               + m * 32 + ((lane >> 3) & 1) * 16]);
                LDMX4(vf[0][0], vf[0][1], vf[1][0], vf[1][1], a0);
                LDMX4(vf[2][0], vf[2][1], vf[3][0], vf[3][1], a0 + 16 * 272);
            }

            // O += P.V
            #pragma unroll
            for (int mt = 0; mt < 2; mt++)
                #pragma unroll
                for (int dt = 0; dt < 4; dt++)
                    mma16816(o[mt][dt][0], o[mt][dt][1], o[mt][dt][2], o[mt][dt][3],
                             pa[mt][0], pa[mt][1], pa[mt][2], pa[mt][3],
                             vf[dt][0], vf[dt][1]);
        }
        __syncthreads();
    }

    // ---- normalize + write AO[b][n][c] fp16 (row sums already per-thread) ----
    const int b = bh >> 5, area = (bh >> 3) & 3, h = bh & 7;
    #pragma unroll
    for (int mt = 0; mt < 2; mt++) {
        const float inv0 = 1.f / lacc[mt][0];
        const float inv1 = 1.f / lacc[mt][2];
        const int nb = area * NA + i0 + mt * 16;
        __half* outp = g_AOh + ((size_t)b * NPIX + nb) * CCH + h * HD;
        #pragma unroll
        for (int dt = 0; dt < 4; dt++) {
            *(__half2*)(outp + (size_t)(gr    ) * CCH + dt * 8 + 2 * tg) =
                __floats2half2_rn(o[mt][dt][0] * inv0, o[mt][dt][1] * inv0);
            *(__half2*)(outp + (size_t)(gr + 8) * CCH + dt * 8 + 2 * tg) =
                __floats2half2_rn(o[mt][dt][2] * inv1, o[mt][dt][3] * inv1);
        }
    }
}

// ---------------------------------------------------------------------------
// proj_out via mma.sync: out[b,co,n] = Whp[co,:] . AOh[b,n,:] + shp[co]
// ---------------------------------------------------------------------------
__global__ __launch_bounds__(256) void proj_out_mma(float* __restrict__ out)
{
    __shared__ __align__(16) __half Ws[128][72];
    __shared__ __align__(16) __half As[64][72];

    const int b   = blockIdx.z;
    const int co0 = blockIdx.y * 128;
    const int n0  = blockIdx.x * 64;
    const int t    = threadIdx.x;
    const int lane = t & 31, wid = t >> 5;
    const int wo = wid >> 1, wn = wid & 1;
    const int gr = lane >> 2, tg = lane & 3;

    const __half* ab = g_AOh + (size_t)b * NPIX * CCH;

    float acc[2][4][4];
    #pragma unroll
    for (int i = 0; i < 2; i++)
        #pragma unroll
        for (int j = 0; j < 4; j++)
            #pragma unroll
            for (int k = 0; k < 4; k++) acc[i][j][k] = 0.f;

    for (int k0 = 0; k0 < 256; k0 += 64) {
        if (k0) __syncthreads();
        #pragma unroll
        for (int u = 0; u < 4; u++) {
            int idx = t + u * 256;
            int row = idx >> 3, seg = idx & 7;
            *(uint4*)&Ws[row][seg * 8] =
                *(const uint4*)(g_Whp + (size_t)(co0 + row) * 256 + k0 + seg * 8);
        }
        #pragma unroll
        for (int u = 0; u < 2; u++) {
            int idx = t + u * 256;
            int row = idx >> 3, seg = idx & 7;
            *(uint4*)&As[row][seg * 8] =
                *(const uint4*)(ab + (size_t)(n0 + row) * CCH + k0 + seg * 8);
        }
        __syncthreads();

        #pragma unroll
        for (int k16 = 0; k16 < 4; k16++) {
            uint32_t a[2][4];
            #pragma unroll
            for (int ot = 0; ot < 2; ot++) {
                uint32_t addr = cvta_sh(&Ws[wo * 32 + ot * 16 + (lane & 15)]
                                           [k16 * 16 + ((lane >> 4) << 3)]);
                LDMX4(a[ot][0], a[ot][1], a[ot][2], a[ot][3], addr);
            }
            uint32_t bf[2][4];
            #pragma unroll
            for (int nt = 0; nt < 2; nt++) {
                uint32_t addr = cvta_sh(&As[wn * 32 + nt * 16 + ((lane >> 4) << 3) + (lane & 7)]
                                           [k16 * 16 + (lane & 8)]);
                LDMX4(bf[nt][0], bf[nt][1], bf[nt][2], bf[nt][3], addr);
            }
            #pragma unroll
            for (int ot = 0; ot < 2; ot++)
                #pragma unroll
                for (int nt = 0; nt < 2; nt++)
                    #pragma unroll
                    for (int nh = 0; nh < 2; nh++) {
                        int ni = nt * 2 + nh;
                        mma16816(acc[ot][ni][0], acc[ot][ni][1], acc[ot][ni][2], acc[ot][ni][3],
                                 a[ot][0], a[ot][1], a[ot][2], a[ot][3],
                                 bf[nt][nh * 2], bf[nt][nh * 2 + 1]);
                    }
        }
    }

    #pragma unroll
    for (int ot = 0; ot < 2; ot++) {
        const int co = co0 + wo * 32 + ot * 16 + gr;
        const float sh0 = g_shp[co], sh1 = g_shp[co + 8];
        #pragma unroll
        for (int ni = 0; ni < 4; ni++) {
            int n = n0 + wn * 32 + (ni >> 1) * 16 + (ni & 1) * 8 + 2 * tg;
            float2 r0, r1;
            r0.x = acc[ot][ni][0] + sh0; r0.y = acc[ot][ni][1] + sh0;
            r1.x = acc[ot][ni][2] + sh1; r1.y = acc[ot][ni][3] + sh1;
            *(float2*)(out + ((size_t)(b * CCH + co    )) * NPIX + n) = r0;
            *(float2*)(out + ((size_t)(b * CCH + co + 8)) * NPIX + n) = r1;
        }
    }
}

// ---------------------------------------------------------------------------
extern "C" void kernel_launch(void* const* d_in, const int* in_sizes, int n_in,
                              void* d_out, int out_size)
{
    const float* x    = (const float*)d_in[0];
    const float* w_qk = (const float*)d_in[1];
    const float* g_qk = (const float*)d_in[2];
    const float* b_qk = (const float*)d_in[3];
    const float* m_qk = (const float*)d_in[4];
    const float* v_qk = (const float*)d_in[5];
    const float* w_v  = (const float*)d_in[6];
    const float* g_v  = (const float*)d_in[7];
    const float* b_v  = (const float*)d_in[8];
    const float* m_v  = (const float*)d_in[9];
    const float* v_v  = (const float*)d_in[10];
    const float* w_p  = (const float*)d_in[11];
    const float* g_p  = (const float*)d_in[12];
    const float* b_p  = (const float*)d_in[13];
    const float* m_p  = (const float*)d_in[14];
    const float* v_p  = (const float*)d_in[15];
    float* out = (float*)d_out;

    prep_w<<<1024, 256>>>(w_qk, g_qk, b_qk, m_qk, v_qk,
                          w_v,  g_v,  b_v,  m_v,  v_v,
                          w_p,  g_p,  b_p,  m_p,  v_p);
    prep_x<<<2048, 256>>>(x);
    proj_in_mma<<<dim3(64, 6, BATCH), 256>>>();
    attn_mma<<<dim3(4, 64), 256>>>();
    proj_out_mma<<<dim3(64, 2, BATCH), 256>>>(out);
}